// round 5
// baseline (speedup 1.0000x reference)
#include <cuda_runtime.h>
#include <math.h>
#include <stdint.h>

// Problem dims (fixed by reference)
#define BB   4
#define SS   2048
#define DD   1024
#define HH   16
#define DK   64
#define DFF  4096
#define NROW (BB*SS)          // 8192
#define LEPS 1e-6f

// ---------------- scratch (static __device__, no allocations) ----------------
__device__ float g_xn  [(size_t)NROW * DD];
__device__ float g_q   [(size_t)NROW * DD];
__device__ float g_k   [(size_t)NROW * DD];
__device__ float g_v   [(size_t)NROW * DD];
__device__ float g_attn[(size_t)NROW * DD];
__device__ float g_x1  [(size_t)NROW * DD];
__device__ float g_h   [(size_t)NROW * DFF];

// ---------------- helpers -----------------------------------------------------
__device__ __forceinline__ uint32_t f2tf(float f) {
    uint32_t u;
    asm("cvt.rna.tf32.f32 %0, %1;" : "=r"(u) : "f"(f));
    return u;
}

#define MMA_TF32(d, a, b)                                                     \
    asm volatile("mma.sync.aligned.m16n8k8.row.col.f32.tf32.tf32.f32 "        \
                 "{%0,%1,%2,%3},{%4,%5,%6,%7},{%8,%9},{%0,%1,%2,%3};"         \
                 : "+f"(d[0]), "+f"(d[1]), "+f"(d[2]), "+f"(d[3])             \
                 : "r"(a[0]), "r"(a[1]), "r"(a[2]), "r"(a[3]),                \
                   "r"(b[0]), "r"(b[1]))

// ---------------- LayerNorm (ddof=1, divide by std+eps) ----------------------
__global__ void ln_kernel(const float* __restrict__ x,
                          const float* __restrict__ w,
                          const float* __restrict__ b,
                          float* __restrict__ y)
{
    int row = blockIdx.x;
    const float* xr = x + (size_t)row * DD;
    int c = threadIdx.x * 4;
    float4 v = *(const float4*)(xr + c);
    float s  = v.x + v.y + v.z + v.w;
    float sq = v.x*v.x + v.y*v.y + v.z*v.z + v.w*v.w;
    #pragma unroll
    for (int o = 16; o; o >>= 1) {
        s  += __shfl_xor_sync(0xffffffffu, s,  o);
        sq += __shfl_xor_sync(0xffffffffu, sq, o);
    }
    __shared__ float ssm[8], sqm[8];
    int wid = threadIdx.x >> 5, lid = threadIdx.x & 31;
    if (lid == 0) { ssm[wid] = s; sqm[wid] = sq; }
    __syncthreads();
    if (wid == 0) {
        float a = (lid < 8) ? ssm[lid] : 0.f;
        float q = (lid < 8) ? sqm[lid] : 0.f;
        #pragma unroll
        for (int o = 16; o; o >>= 1) {
            a += __shfl_xor_sync(0xffffffffu, a, o);
            q += __shfl_xor_sync(0xffffffffu, q, o);
        }
        if (lid == 0) { ssm[0] = a; sqm[0] = q; }
    }
    __syncthreads();
    float sum = ssm[0], sumsq = sqm[0];
    float mean = sum * (1.0f / DD);
    float var  = (sumsq - sum * mean) * (1.0f / (DD - 1));
    float inv  = 1.0f / (sqrtf(var) + LEPS);

    float4 wv = *(const float4*)(w + c);
    float4 bv = *(const float4*)(b + c);
    float4 out;
    out.x = wv.x * (v.x - mean) * inv + bv.x;
    out.y = wv.y * (v.y - mean) * inv + bv.y;
    out.z = wv.z * (v.z - mean) * inv + bv.z;
    out.w = wv.w * (v.w - mean) * inv + bv.w;
    *(float4*)(y + (size_t)row * DD + c) = out;
}

// ---------------- TF32 tensor-core GEMM, fragment-major smem ------------------
// C[N,M] = A[N,K] @ W[K,M] + bias (+relu / +resid)
// 128x128 tile, BK=16, 8 warps (2x4), warp tile 64x32.
// Smem stores fragments in [kstep][block][lane][reg] order:
//   A reads = LDS.128, B reads = LDS.64, conflict-free.
template<int MODE>
__device__ __forceinline__
void tgemm_body(const float* __restrict__ A, const float* __restrict__ W,
                const float* __restrict__ bias, const float* __restrict__ resid,
                float* __restrict__ C, int K, int M, int bx, int by)
{
    // Af[buf][ks][im(8)][lane(32)][reg(4)]  Bf[buf][ks][jn(16)][lane(32)][reg(2)]
    __shared__ __align__(16) uint32_t Af[2][2][8][32][4];
    __shared__ __align__(16) uint32_t Bf[2][2][16][32][2];

    int tid  = threadIdx.x;
    int lane = tid & 31, warp = tid >> 5;
    int wm = warp >> 2, wn = warp & 3;
    int g = lane >> 2, t = lane & 3;
    int row0 = by * 128, col0 = bx * 128;

    // A staging: thread covers row ar, kstep aks, 8 k-values
    int ar = tid >> 1, aks = tid & 1;
    int a_im = ar >> 4, a_g = ar & 7, a_half = (ar >> 3) & 1;
    const float* Aptr = A + (size_t)(row0 + ar) * K + aks * 8;

    // B staging: thread covers k-rows wk & wk+8, 4 cols
    int wk = tid >> 5;                 // 0..7
    int wc = (tid & 31) * 4;
    int b_reg = wk >> 2, b_tq = wk & 3;
    const float* Wptr0 = W + (size_t)wk * M + col0 + wc;
    const float* Wptr1 = W + (size_t)(wk + 8) * M + col0 + wc;

    float acc[4][4][4];
    #pragma unroll
    for (int i = 0; i < 4; i++)
        #pragma unroll
        for (int j = 0; j < 4; j++)
            #pragma unroll
            for (int r = 0; r < 4; r++) acc[i][j][r] = 0.f;

    // ---- stage tile 0 into buf 0 ----
    {
        float av[8];
        *(float4*)&av[0] = *(const float4*)(Aptr);
        *(float4*)&av[4] = *(const float4*)(Aptr + 4);
        #pragma unroll
        for (int kq = 0; kq < 8; kq++) {
            int reg = a_half + 2 * (kq >> 2);
            int ln  = a_g * 4 + (kq & 3);
            Af[0][aks][a_im][ln][reg] = f2tf(av[kq]);
        }
        float w0[4], w1[4];
        *(float4*)w0 = *(const float4*)(Wptr0);
        *(float4*)w1 = *(const float4*)(Wptr1);
        #pragma unroll
        for (int j = 0; j < 4; j++) {
            int lc = wc + j;
            int ln = (lc & 7) * 4 + b_tq;
            Bf[0][0][lc >> 3][ln][b_reg] = f2tf(w0[j]);
            Bf[0][1][lc >> 3][ln][b_reg] = f2tf(w1[j]);
        }
    }
    __syncthreads();

    int buf = 0;
    for (int k0 = 0; k0 < K; k0 += 16) {
        float avn[8], w0n[4], w1n[4];
        const bool more = (k0 + 16) < K;
        if (more) {
            *(float4*)&avn[0] = *(const float4*)(Aptr + k0 + 16);
            *(float4*)&avn[4] = *(const float4*)(Aptr + k0 + 20);
            *(float4*)w0n = *(const float4*)(Wptr0 + (size_t)(k0 + 16) * M);
            *(float4*)w1n = *(const float4*)(Wptr1 + (size_t)(k0 + 16) * M);
        }

        #pragma unroll
        for (int ks = 0; ks < 2; ks++) {
            uint32_t afr[4][4], bfr[4][2];
            #pragma unroll
            for (int im2 = 0; im2 < 4; im2++)
                *(uint4*)&afr[im2][0] =
                    *(const uint4*)&Af[buf][ks][wm * 4 + im2][lane][0];
            #pragma unroll
            for (int jn2 = 0; jn2 < 4; jn2++)
                *(uint2*)&bfr[jn2][0] =
                    *(const uint2*)&Bf[buf][ks][wn * 4 + jn2][lane][0];
            #pragma unroll
            for (int im2 = 0; im2 < 4; im2++)
                #pragma unroll
                for (int jn2 = 0; jn2 < 4; jn2++)
                    MMA_TF32(acc[im2][jn2], afr[im2], bfr[jn2]);
        }

        if (more) {
            int nb = buf ^ 1;
            #pragma unroll
            for (int kq = 0; kq < 8; kq++) {
                int reg = a_half + 2 * (kq >> 2);
                int ln  = a_g * 4 + (kq & 3);
                Af[nb][aks][a_im][ln][reg] = f2tf(avn[kq]);
            }
            #pragma unroll
            for (int j = 0; j < 4; j++) {
                int lc = wc + j;
                int ln = (lc & 7) * 4 + b_tq;
                Bf[nb][0][lc >> 3][ln][b_reg] = f2tf(w0n[j]);
                Bf[nb][1][lc >> 3][ln][b_reg] = f2tf(w1n[j]);
            }
            __syncthreads();
            buf = nb;
        }
    }

    // epilogue (fragment: c0,c1 row g cols 2t,2t+1; c2,c3 row g+8)
    #pragma unroll
    for (int im = 0; im < 4; im++) {
        int rA = row0 + wm * 64 + im * 16 + g;
        int rB = rA + 8;
        #pragma unroll
        for (int jn = 0; jn < 4; jn++) {
            int col = col0 + wn * 32 + jn * 8 + 2 * t;
            float bx0 = bias[col], bx1 = bias[col + 1];
            float v0 = acc[im][jn][0] + bx0;
            float v1 = acc[im][jn][1] + bx1;
            float v2 = acc[im][jn][2] + bx0;
            float v3 = acc[im][jn][3] + bx1;
            if (MODE == 1) {
                v0 = fmaxf(v0, 0.f); v1 = fmaxf(v1, 0.f);
                v2 = fmaxf(v2, 0.f); v3 = fmaxf(v3, 0.f);
            }
            size_t oA = (size_t)rA * M + col;
            size_t oB = (size_t)rB * M + col;
            if (MODE == 2) {
                float2 r0 = *(const float2*)(resid + oA);
                float2 r1 = *(const float2*)(resid + oB);
                v0 += r0.x; v1 += r0.y; v2 += r1.x; v3 += r1.y;
            }
            *(float2*)(C + oA) = make_float2(v0, v1);
            *(float2*)(C + oB) = make_float2(v2, v3);
        }
    }
}

template<int MODE>
__global__ __launch_bounds__(256, 2)
void tgemm_kernel(const float* __restrict__ A, const float* __restrict__ W,
                  const float* __restrict__ bias, const float* __restrict__ resid,
                  float* __restrict__ C, int K, int M)
{
    tgemm_body<MODE>(A, W, bias, resid, C, K, M, blockIdx.x, blockIdx.y);
}

__global__ __launch_bounds__(256, 2)
void qkv_kernel(const float* __restrict__ A,
                const float* __restrict__ wq, const float* __restrict__ bq,
                const float* __restrict__ wk, const float* __restrict__ bk,
                const float* __restrict__ wv, const float* __restrict__ bv,
                float* __restrict__ q, float* __restrict__ k, float* __restrict__ v)
{
    const float* W; const float* bias; float* C;
    if (blockIdx.z == 0)      { W = wq; bias = bq; C = q; }
    else if (blockIdx.z == 1) { W = wk; bias = bk; C = k; }
    else                      { W = wv; bias = bv; C = v; }
    tgemm_body<0>(A, W, bias, nullptr, C, DD, DD, blockIdx.x, blockIdx.y);
}

// ---------------- Tensorized flash attention ----------------------------------
// Br=Bc=64, dk=64, 256 threads (8 warps: 2(m) x 4(n)), tf32 MMA for QK^T and PV.
// Fragment-major smem for Q, K, V, P; S round-trips through smem for the
// scalar online softmax.
//
// smem layout (u32 words):
#define F_QF 0          // Qf: 8ks x 4im x 32 x 4 = 4096
#define F_KF 4096       // Kf: 8ks x 8jn x 32 x 2 = 4096
#define F_VF 8192       // Vf: 8ks x 8jn x 32 x 2 = 4096
#define F_PF 12288      // Pf: 8ks x 4im x 32 x 4 = 4096
#define F_SS 16384      // Ss: 64 x 68 fp32       = 4352
#define F_SC 20736      // sc[64]
#define F_LI 20800      // linv[64]
#define F_MS 20864      // mask[64]
#define F_TOT 20928     // *4 = 83712 bytes

__global__ __launch_bounds__(256)
void flash_kernel(const float* __restrict__ Q, const float* __restrict__ Kk,
                  const float* __restrict__ V, const int* __restrict__ mask,
                  float* __restrict__ O)
{
    extern __shared__ __align__(16) uint32_t smu[];
    uint32_t* Qf = smu + F_QF;
    uint32_t* Kf = smu + F_KF;
    uint32_t* Vf = smu + F_VF;
    uint32_t* Pf = smu + F_PF;
    float*    Ss = (float*)(smu + F_SS);
    float*    sc = (float*)(smu + F_SC);
    float*    li = (float*)(smu + F_LI);
    int*      ms = (int*)  (smu + F_MS);

    int tid  = threadIdx.x;
    int lane = tid & 31, warp = tid >> 5;
    int wm = warp >> 2, wn = warp & 3;   // 2 x 4 warp grid
    int g = lane >> 2, t = lane & 3;
    int ty = tid >> 4, tx = tid & 15;    // softmax role

    int q0 = blockIdx.x * 64;
    int h  = blockIdx.y;
    int b  = blockIdx.z;

    const float* Qb = Q  + ((size_t)(b * SS + q0)) * DD + h * DK;
    const float* Kb = Kk + ((size_t)b * SS) * DD + h * DK;
    const float* Vb = V  + ((size_t)b * SS) * DD + h * DK;
    const int*   mb = mask + b * SS;

    // staging role: row r (0..63), 16 d-values starting at dbase
    int sr = tid >> 2, dbase = (tid & 3) * 16;
    int s_jn = sr >> 3, s_g = sr & 7;                 // K: n-dims
    int s_ks = sr >> 3, s_tq = sr & 3, s_reg = (sr >> 2) & 1;  // V: k-dims
    int q_im = sr >> 4, q_g = sr & 7, q_half = (sr >> 3) & 1;  // Q: m-dims

    // ---- stage Q (once), pre-scaled by 1/sqrt(dk) ----
    #pragma unroll
    for (int cch = 0; cch < 4; cch++) {
        int d0 = dbase + cch * 4;
        float4 v = *(const float4*)(Qb + (size_t)sr * DD + d0);
        float vv[4] = {v.x, v.y, v.z, v.w};
        #pragma unroll
        for (int e = 0; e < 4; e++) {
            int d = d0 + e;
            int reg = q_half + 2 * ((d >> 2) & 1);
            int ln  = q_g * 4 + (d & 3);
            Qf[(((d >> 3) * 4 + q_im) * 32 + ln) * 4 + reg] = f2tf(vv[e] * 0.125f);
        }
    }

    // persistent state
    float acc_o[2][2][4];
    #pragma unroll
    for (int i = 0; i < 2; i++)
        #pragma unroll
        for (int j = 0; j < 2; j++)
            #pragma unroll
            for (int r = 0; r < 4; r++) acc_o[i][j][r] = 0.f;
    float mrow[4], lrow[4];
    #pragma unroll
    for (int i = 0; i < 4; i++) { mrow[i] = -INFINITY; lrow[i] = 0.f; }

    for (int kt = 0; kt < SS / 64; kt++) {
        int k0 = kt * 64;
        __syncthreads();   // prior PV reads done

        // ---- stage K, V fragments ----
        #pragma unroll
        for (int cch = 0; cch < 4; cch++) {
            int d0 = dbase + cch * 4;
            float4 kv = *(const float4*)(Kb + (size_t)(k0 + sr) * DD + d0);
            float4 vv = *(const float4*)(Vb + (size_t)(k0 + sr) * DD + d0);
            float ka[4] = {kv.x, kv.y, kv.z, kv.w};
            float va[4] = {vv.x, vv.y, vv.z, vv.w};
            #pragma unroll
            for (int e = 0; e < 4; e++) {
                int d = d0 + e;
                // K: k-dim = d, n-dim = sr
                int kreg = (d >> 2) & 1;
                int kln  = s_g * 4 + (d & 3);
                Kf[(((d >> 3) * 8 + s_jn) * 32 + kln) * 2 + kreg] = f2tf(ka[e]);
                // V: k-dim = sr, n-dim = d
                int vln = (d & 7) * 4 + s_tq;
                Vf[((s_ks * 8 + (d >> 3)) * 32 + vln) * 2 + s_reg] = f2tf(va[e]);
            }
        }
        if (tid < 64) ms[tid] = mb[k0 + tid];
        __syncthreads();

        // ---- S = Q @ K^T via MMA ----
        float sacc[2][2][4];
        #pragma unroll
        for (int i = 0; i < 2; i++)
            #pragma unroll
            for (int j = 0; j < 2; j++)
                #pragma unroll
                for (int r = 0; r < 4; r++) sacc[i][j][r] = 0.f;
        #pragma unroll
        for (int ks = 0; ks < 8; ks++) {
            uint32_t qa[2][4], kb2[2][2];
            #pragma unroll
            for (int im2 = 0; im2 < 2; im2++)
                *(uint4*)&qa[im2][0] =
                    *(const uint4*)&Qf[((ks * 4 + wm * 2 + im2) * 32 + lane) * 4];
            #pragma unroll
            for (int jn2 = 0; jn2 < 2; jn2++)
                *(uint2*)&kb2[jn2][0] =
                    *(const uint2*)&Kf[((ks * 8 + wn * 2 + jn2) * 32 + lane) * 2];
            #pragma unroll
            for (int im2 = 0; im2 < 2; im2++)
                #pragma unroll
                for (int jn2 = 0; jn2 < 2; jn2++)
                    MMA_TF32(sacc[im2][jn2], qa[im2], kb2[jn2]);
        }
        // write S tile to smem
        #pragma unroll
        for (int im2 = 0; im2 < 2; im2++) {
            int row = wm * 32 + im2 * 16 + g;
            #pragma unroll
            for (int jn2 = 0; jn2 < 2; jn2++) {
                int col = wn * 16 + jn2 * 8 + 2 * t;
                Ss[row * 68 + col]           = sacc[im2][jn2][0];
                Ss[row * 68 + col + 1]       = sacc[im2][jn2][1];
                Ss[(row + 8) * 68 + col]     = sacc[im2][jn2][2];
                Ss[(row + 8) * 68 + col + 1] = sacc[im2][jn2][3];
            }
        }
        __syncthreads();

        // ---- scalar online softmax (rows ty*4+i, cols tx*4+j) ----
        float s4[4][4];
        #pragma unroll
        for (int i = 0; i < 4; i++) {
            float4 r4 = *(const float4*)&Ss[(ty * 4 + i) * 68 + tx * 4];
            s4[i][0] = r4.x; s4[i][1] = r4.y; s4[i][2] = r4.z; s4[i][3] = r4.w;
        }
        #pragma unroll
        for (int i = 0; i < 4; i++)
            #pragma unroll
            for (int j = 0; j < 4; j++)
                if (ms[tx * 4 + j] == 0) s4[i][j] = -INFINITY;

        float scv[4];
        #pragma unroll
        for (int i = 0; i < 4; i++) {
            float mx = fmaxf(fmaxf(s4[i][0], s4[i][1]), fmaxf(s4[i][2], s4[i][3]));
            #pragma unroll
            for (int off = 8; off; off >>= 1)
                mx = fmaxf(mx, __shfl_xor_sync(0xffffffffu, mx, off));
            float mn = fmaxf(mrow[i], mx);
            float scl = (mrow[i] == -INFINITY) ? 0.f : __expf(mrow[i] - mn);
            float sum = 0.f;
            #pragma unroll
            for (int j = 0; j < 4; j++) {
                float p = __expf(s4[i][j] - mn);
                s4[i][j] = p; sum += p;
            }
            #pragma unroll
            for (int off = 8; off; off >>= 1)
                sum += __shfl_xor_sync(0xffffffffu, sum, off);
            lrow[i] = lrow[i] * scl + sum;
            mrow[i] = mn;
            scv[i] = scl;
        }
        // write P fragments + rescale factors
        #pragma unroll
        for (int i = 0; i < 4; i++) {
            int row = ty * 4 + i;
            int p_im = row >> 4, p_g = row & 7, p_half = (row >> 3) & 1;
            #pragma unroll
            for (int j = 0; j < 4; j++) {
                int col = tx * 4 + j;
                int reg = p_half + 2 * ((col >> 2) & 1);
                int ln  = p_g * 4 + (col & 3);
                Pf[(((col >> 3) * 4 + p_im) * 32 + ln) * 4 + reg] = f2tf(s4[i][j]);
            }
            if (tx == 0) sc[row] = scv[i];
        }
        __syncthreads();

        // ---- O = O*sc + P @ V via MMA ----
        #pragma unroll
        for (int im2 = 0; im2 < 2; im2++) {
            int rl = wm * 32 + im2 * 16 + g;
            float s0 = sc[rl], s1 = sc[rl + 8];
            #pragma unroll
            for (int jn2 = 0; jn2 < 2; jn2++) {
                acc_o[im2][jn2][0] *= s0; acc_o[im2][jn2][1] *= s0;
                acc_o[im2][jn2][2] *= s1; acc_o[im2][jn2][3] *= s1;
            }
        }
        #pragma unroll
        for (int ks = 0; ks < 8; ks++) {
            uint32_t pa[2][4], vb2[2][2];
            #pragma unroll
            for (int im2 = 0; im2 < 2; im2++)
                *(uint4*)&pa[im2][0] =
                    *(const uint4*)&Pf[((ks * 4 + wm * 2 + im2) * 32 + lane) * 4];
            #pragma unroll
            for (int jn2 = 0; jn2 < 2; jn2++)
                *(uint2*)&vb2[jn2][0] =
                    *(const uint2*)&Vf[((ks * 8 + wn * 2 + jn2) * 32 + lane) * 2];
            #pragma unroll
            for (int im2 = 0; im2 < 2; im2++)
                #pragma unroll
                for (int jn2 = 0; jn2 < 2; jn2++)
                    MMA_TF32(acc_o[im2][jn2], pa[im2], vb2[jn2]);
        }
    }

    // ---- finalize ----
    __syncthreads();
    #pragma unroll
    for (int i = 0; i < 4; i++)
        if (tx == 0) li[ty * 4 + i] = 1.0f / lrow[i];
    __syncthreads();

    float* Ob = O + ((size_t)(b * SS + q0)) * DD + h * DK;
    #pragma unroll
    for (int im2 = 0; im2 < 2; im2++) {
        int rl = wm * 32 + im2 * 16 + g;
        float il0 = li[rl], il1 = li[rl + 8];
        #pragma unroll
        for (int jn2 = 0; jn2 < 2; jn2++) {
            int col = wn * 16 + jn2 * 8 + 2 * t;
            *(float2*)(Ob + (size_t)rl * DD + col) =
                make_float2(acc_o[im2][jn2][0] * il0, acc_o[im2][jn2][1] * il0);
            *(float2*)(Ob + (size_t)(rl + 8) * DD + col) =
                make_float2(acc_o[im2][jn2][2] * il1, acc_o[im2][jn2][3] * il1);
        }
    }
}

// ---------------- launch ------------------------------------------------------
extern "C" void kernel_launch(void* const* d_in, const int* in_sizes, int n_in,
                              void* d_out, int out_size)
{
    const float* x    = (const float*)d_in[0];
    const int*   mask = (const int*)  d_in[1];
    const float* wq   = (const float*)d_in[2];
    const float* bq   = (const float*)d_in[3];
    const float* wk   = (const float*)d_in[4];
    const float* bk   = (const float*)d_in[5];
    const float* wv   = (const float*)d_in[6];
    const float* bv   = (const float*)d_in[7];
    const float* wo   = (const float*)d_in[8];
    const float* bo   = (const float*)d_in[9];
    const float* w1   = (const float*)d_in[10];
    const float* b1   = (const float*)d_in[11];
    const float* w2   = (const float*)d_in[12];
    const float* b2   = (const float*)d_in[13];
    const float* ln1w = (const float*)d_in[14];
    const float* ln1b = (const float*)d_in[15];
    const float* ln2w = (const float*)d_in[16];
    const float* ln2b = (const float*)d_in[17];
    float* out = (float*)d_out;

    float *xn, *q, *k, *v, *attn, *x1, *hb;
    cudaGetSymbolAddress((void**)&xn,   g_xn);
    cudaGetSymbolAddress((void**)&q,    g_q);
    cudaGetSymbolAddress((void**)&k,    g_k);
    cudaGetSymbolAddress((void**)&v,    g_v);
    cudaGetSymbolAddress((void**)&attn, g_attn);
    cudaGetSymbolAddress((void**)&x1,   g_x1);
    cudaGetSymbolAddress((void**)&hb,   g_h);

    cudaFuncSetAttribute(flash_kernel,
                         cudaFuncAttributeMaxDynamicSharedMemorySize,
                         F_TOT * (int)sizeof(uint32_t));

    dim3 gD  (DD  / 128, NROW / 128);
    dim3 gQKV(DD  / 128, NROW / 128, 3);
    dim3 gF  (DFF / 128, NROW / 128);
    dim3 gAtt(SS / 64, HH, BB);

    ln_kernel<<<NROW, 256>>>(x, ln1w, ln1b, xn);
    qkv_kernel<<<gQKV, 256>>>(xn, wq, bq, wk, bk, wv, bv, q, k, v);
    flash_kernel<<<gAtt, 256, F_TOT * sizeof(uint32_t)>>>(q, k, v, mask, attn);
    tgemm_kernel<2><<<gD, 256>>>(attn, wo, bo, x, x1, DD, DD);
    ln_kernel<<<NROW, 256>>>(x1, ln2w, ln2b, xn);
    tgemm_kernel<1><<<gF, 256>>>(xn, w1, b1, nullptr, hb, DD, DFF);
    tgemm_kernel<2><<<gD, 256>>>(hb, w2, b2, x1, out, DFF, DD);
}

// round 6
// speedup vs baseline: 1.9306x; 1.9306x over previous
#include <cuda_runtime.h>
#include <math.h>
#include <stdint.h>

// Problem dims (fixed by reference)
#define BB   4
#define SS   2048
#define DD   1024
#define HH   16
#define DK   64
#define DFF  4096
#define NROW (BB*SS)          // 8192
#define LEPS 1e-6f

// ---------------- scratch (static __device__, no allocations) ----------------
__device__ float g_xn  [(size_t)NROW * DD];
__device__ float g_q   [(size_t)NROW * DD];
__device__ float g_k   [(size_t)NROW * DD];
__device__ float g_v   [(size_t)NROW * DD];
__device__ float g_attn[(size_t)NROW * DD];
__device__ float g_x1  [(size_t)NROW * DD];
__device__ float g_h   [(size_t)NROW * DFF];
// pre-laid tf32 weight fragments: wq,wk,wv,wo (1M each), w1 (4M), w2 (4M)
__device__ uint32_t g_wf[(size_t)13 * 1024 * 1024];

#define WF_Q  ((size_t)0)
#define WF_K  ((size_t)1  * 1024 * 1024)
#define WF_V  ((size_t)2  * 1024 * 1024)
#define WF_O  ((size_t)3  * 1024 * 1024)
#define WF_1  ((size_t)4  * 1024 * 1024)
#define WF_2  ((size_t)8  * 1024 * 1024)

// ---------------- helpers -----------------------------------------------------
__device__ __forceinline__ uint32_t f2tf(float f) {
    uint32_t u;
    asm("cvt.rna.tf32.f32 %0, %1;" : "=r"(u) : "f"(f));
    return u;
}

#define MMA_TF32(d, a, b)                                                     \
    asm volatile("mma.sync.aligned.m16n8k8.row.col.f32.tf32.tf32.f32 "        \
                 "{%0,%1,%2,%3},{%4,%5,%6,%7},{%8,%9},{%0,%1,%2,%3};"         \
                 : "+f"(d[0]), "+f"(d[1]), "+f"(d[2]), "+f"(d[3])             \
                 : "r"(a[0]), "r"(a[1]), "r"(a[2]), "r"(a[3]),                \
                   "r"(b[0]), "r"(b[1]))

#define LDSM_X4(r0, r1, r2, r3, addr)                                         \
    asm volatile("ldmatrix.sync.aligned.m8n8.x4.shared.b16 {%0,%1,%2,%3}, [%4];" \
                 : "=r"(r0), "=r"(r1), "=r"(r2), "=r"(r3) : "r"(addr))

// ---------------- weight fragment pre-layout ----------------------------------
// Wf[kb][mb][lane*2+reg] = tf32( W[kb*8 + (lane&3) + reg*4][mb*8 + (lane>>2)] )
__global__ void wlayout_kernel(const float* __restrict__ W,
                               uint32_t* __restrict__ Wf, int M)
{
    int mb = blockIdx.x, kb = blockIdx.y;
    int tid = threadIdx.x;                 // 64 threads
    int lane = tid & 31, reg = tid >> 5;
    int t = lane & 3, g = lane >> 2;
    float v = W[(size_t)(kb * 8 + t + reg * 4) * M + mb * 8 + g];
    Wf[(((size_t)kb * (M >> 3)) + mb) * 64 + lane * 2 + reg] = f2tf(v);
}

// ---------------- LayerNorm (ddof=1, divide by std+eps) ----------------------
__global__ void ln_kernel(const float* __restrict__ x,
                          const float* __restrict__ w,
                          const float* __restrict__ b,
                          float* __restrict__ y)
{
    int row = blockIdx.x;
    const float* xr = x + (size_t)row * DD;
    int c = threadIdx.x * 4;
    float4 v = *(const float4*)(xr + c);
    float s  = v.x + v.y + v.z + v.w;
    float sq = v.x*v.x + v.y*v.y + v.z*v.z + v.w*v.w;
    #pragma unroll
    for (int o = 16; o; o >>= 1) {
        s  += __shfl_xor_sync(0xffffffffu, s,  o);
        sq += __shfl_xor_sync(0xffffffffu, sq, o);
    }
    __shared__ float ssm[8], sqm[8];
    int wid = threadIdx.x >> 5, lid = threadIdx.x & 31;
    if (lid == 0) { ssm[wid] = s; sqm[wid] = sq; }
    __syncthreads();
    if (wid == 0) {
        float a = (lid < 8) ? ssm[lid] : 0.f;
        float q = (lid < 8) ? sqm[lid] : 0.f;
        #pragma unroll
        for (int o = 16; o; o >>= 1) {
            a += __shfl_xor_sync(0xffffffffu, a, o);
            q += __shfl_xor_sync(0xffffffffu, q, o);
        }
        if (lid == 0) { ssm[0] = a; sqm[0] = q; }
    }
    __syncthreads();
    float sum = ssm[0], sumsq = sqm[0];
    float mean = sum * (1.0f / DD);
    float var  = (sumsq - sum * mean) * (1.0f / (DD - 1));
    float inv  = 1.0f / (sqrtf(var) + LEPS);

    float4 wv = *(const float4*)(w + c);
    float4 bv = *(const float4*)(b + c);
    float4 out;
    out.x = wv.x * (v.x - mean) * inv + bv.x;
    out.y = wv.y * (v.y - mean) * inv + bv.y;
    out.z = wv.z * (v.z - mean) * inv + bv.z;
    out.w = wv.w * (v.w - mean) * inv + bv.w;
    *(float4*)(y + (size_t)row * DD + c) = out;
}

// ---------------- TF32 GEMM: ldmatrix A + pre-laid fragment B -----------------
// C[N,M] = A[N,K] @ W[K,M] + bias (+relu / +resid)
// 128x128 tile, BK=16, 8 warps (2x4), warp tile 64x32, double-buffered.
template<int MODE>
__device__ __forceinline__
void tgemm_body(const float* __restrict__ A, const uint32_t* __restrict__ Wf,
                const float* __restrict__ bias, const float* __restrict__ resid,
                float* __restrict__ C, int K, int M, int bx, int by)
{
    __shared__ __align__(16) uint32_t As[2][128][20];   // row-major m x k(+pad)
    __shared__ __align__(16) uint32_t Bf[2][2048];      // [ks][jn][lane][reg]

    int tid  = threadIdx.x;
    int lane = tid & 31, warp = tid >> 5;
    int wm = warp >> 2, wn = warp & 3;
    int g = lane >> 2, t = lane & 3;
    int row0 = by * 128, col0 = bx * 128;
    const int MB = M >> 3;

    // A staging: thread -> row ar, k-half aks (8 k-values)
    int ar = tid >> 1, aks = tid & 1;
    const float* Aptr = A + (size_t)(row0 + ar) * K + aks * 8;

    // B staging: pure contiguous copy of 2 x 1024 u32 from fragment gmem
    int bks = tid >> 7;                    // 0..1
    int bidx = (tid & 127) * 8;            // 8 u32 per thread
    const uint32_t* Wfp = Wf + ((size_t)bks * MB + (col0 >> 3)) * 64 + bidx;
    const size_t wstep = (size_t)2 * MB * 64;   // advance per BK=16

    // ldmatrix address pieces (per lane)
    int lm_tile = lane >> 3, lm_r = lane & 7;
    int lm_row_base = wm * 64 + (lm_tile & 1) * 8 + lm_r;
    int lm_colw = (lm_tile >> 1) * 4;

    float acc[4][4][4];
    #pragma unroll
    for (int i = 0; i < 4; i++)
        #pragma unroll
        for (int j = 0; j < 4; j++)
            #pragma unroll
            for (int r = 0; r < 4; r++) acc[i][j][r] = 0.f;

    // ---- stage tile 0 -> buf 0 ----
    {
        float4 a0 = *(const float4*)(Aptr);
        float4 a1 = *(const float4*)(Aptr + 4);
        uint32_t aw[8];
        aw[0]=f2tf(a0.x); aw[1]=f2tf(a0.y); aw[2]=f2tf(a0.z); aw[3]=f2tf(a0.w);
        aw[4]=f2tf(a1.x); aw[5]=f2tf(a1.y); aw[6]=f2tf(a1.z); aw[7]=f2tf(a1.w);
        *(uint4*)&As[0][ar][aks * 8]     = *(uint4*)&aw[0];
        *(uint4*)&As[0][ar][aks * 8 + 4] = *(uint4*)&aw[4];
        uint4 b0 = *(const uint4*)(Wfp);
        uint4 b1 = *(const uint4*)(Wfp + 4);
        *(uint4*)&Bf[0][bks * 1024 + bidx]     = b0;
        *(uint4*)&Bf[0][bks * 1024 + bidx + 4] = b1;
    }
    __syncthreads();

    int buf = 0;
    for (int k0 = 0; k0 < K; k0 += 16) {
        float4 a0n, a1n; uint4 b0n, b1n;
        const bool more = (k0 + 16) < K;
        if (more) {
            a0n = *(const float4*)(Aptr + k0 + 16);
            a1n = *(const float4*)(Aptr + k0 + 20);
            const uint32_t* wp = Wfp + (size_t)((k0 >> 4) + 1) * wstep;
            b0n = *(const uint4*)(wp);
            b1n = *(const uint4*)(wp + 4);
        }

        uint32_t as_base = (uint32_t)__cvta_generic_to_shared(&As[buf][0][0]);
        #pragma unroll
        for (int ks = 0; ks < 2; ks++) {
            uint32_t afr[4][4], bfr[4][2];
            #pragma unroll
            for (int im = 0; im < 4; im++) {
                int row = lm_row_base + im * 16;
                uint32_t addr = as_base + (uint32_t)(row * 20 + ks * 8 + lm_colw) * 4u;
                LDSM_X4(afr[im][0], afr[im][1], afr[im][2], afr[im][3], addr);
            }
            #pragma unroll
            for (int jn = 0; jn < 4; jn++)
                *(uint2*)&bfr[jn][0] =
                    *(const uint2*)&Bf[buf][ks * 1024 + (wn * 4 + jn) * 64 + lane * 2];
            #pragma unroll
            for (int im = 0; im < 4; im++)
                #pragma unroll
                for (int jn = 0; jn < 4; jn++)
                    MMA_TF32(acc[im][jn], afr[im], bfr[jn]);
        }

        if (more) {
            int nb = buf ^ 1;
            uint32_t aw[8];
            aw[0]=f2tf(a0n.x); aw[1]=f2tf(a0n.y); aw[2]=f2tf(a0n.z); aw[3]=f2tf(a0n.w);
            aw[4]=f2tf(a1n.x); aw[5]=f2tf(a1n.y); aw[6]=f2tf(a1n.z); aw[7]=f2tf(a1n.w);
            *(uint4*)&As[nb][ar][aks * 8]     = *(uint4*)&aw[0];
            *(uint4*)&As[nb][ar][aks * 8 + 4] = *(uint4*)&aw[4];
            *(uint4*)&Bf[nb][bks * 1024 + bidx]     = b0n;
            *(uint4*)&Bf[nb][bks * 1024 + bidx + 4] = b1n;
            __syncthreads();
            buf = nb;
        }
    }

    // epilogue (fragment: c0,c1 = row g cols 2t,2t+1; c2,c3 = row g+8)
    #pragma unroll
    for (int im = 0; im < 4; im++) {
        int rA = row0 + wm * 64 + im * 16 + g;
        int rB = rA + 8;
        #pragma unroll
        for (int jn = 0; jn < 4; jn++) {
            int col = col0 + wn * 32 + jn * 8 + 2 * t;
            float bx0 = bias[col], bx1 = bias[col + 1];
            float v0 = acc[im][jn][0] + bx0;
            float v1 = acc[im][jn][1] + bx1;
            float v2 = acc[im][jn][2] + bx0;
            float v3 = acc[im][jn][3] + bx1;
            if (MODE == 1) {
                v0 = fmaxf(v0, 0.f); v1 = fmaxf(v1, 0.f);
                v2 = fmaxf(v2, 0.f); v3 = fmaxf(v3, 0.f);
            }
            size_t oA = (size_t)rA * M + col;
            size_t oB = (size_t)rB * M + col;
            if (MODE == 2) {
                float2 r0 = *(const float2*)(resid + oA);
                float2 r1 = *(const float2*)(resid + oB);
                v0 += r0.x; v1 += r0.y; v2 += r1.x; v3 += r1.y;
            }
            *(float2*)(C + oA) = make_float2(v0, v1);
            *(float2*)(C + oB) = make_float2(v2, v3);
        }
    }
}

template<int MODE>
__global__ __launch_bounds__(256, 2)
void tgemm_kernel(const float* __restrict__ A, const uint32_t* __restrict__ Wf,
                  const float* __restrict__ bias, const float* __restrict__ resid,
                  float* __restrict__ C, int K, int M)
{
    tgemm_body<MODE>(A, Wf, bias, resid, C, K, M, blockIdx.x, blockIdx.y);
}

__global__ __launch_bounds__(256, 2)
void qkv_kernel(const float* __restrict__ A, const uint32_t* __restrict__ wf,
                const float* __restrict__ bq, const float* __restrict__ bk,
                const float* __restrict__ bv,
                float* __restrict__ q, float* __restrict__ k, float* __restrict__ v)
{
    const uint32_t* W; const float* bias; float* C;
    if (blockIdx.z == 0)      { W = wf + WF_Q; bias = bq; C = q; }
    else if (blockIdx.z == 1) { W = wf + WF_K; bias = bk; C = k; }
    else                      { W = wf + WF_V; bias = bv; C = v; }
    tgemm_body<0>(A, W, bias, nullptr, C, DD, DD, blockIdx.x, blockIdx.y);
}

// ---------------- Tensorized flash attention (as R5) ---------------------------
#define F_QF 0
#define F_KF 4096
#define F_VF 8192
#define F_PF 12288
#define F_SS 16384
#define F_SC 20736
#define F_LI 20800
#define F_MS 20864
#define F_TOT 20928

__global__ __launch_bounds__(256)
void flash_kernel(const float* __restrict__ Q, const float* __restrict__ Kk,
                  const float* __restrict__ V, const int* __restrict__ mask,
                  float* __restrict__ O)
{
    extern __shared__ __align__(16) uint32_t smu[];
    uint32_t* Qf = smu + F_QF;
    uint32_t* Kf = smu + F_KF;
    uint32_t* Vf = smu + F_VF;
    uint32_t* Pf = smu + F_PF;
    float*    Ss = (float*)(smu + F_SS);
    float*    sc = (float*)(smu + F_SC);
    float*    li = (float*)(smu + F_LI);
    int*      ms = (int*)  (smu + F_MS);

    int tid  = threadIdx.x;
    int lane = tid & 31, warp = tid >> 5;
    int wm = warp >> 2, wn = warp & 3;
    int g = lane >> 2, t = lane & 3;
    int ty = tid >> 4, tx = tid & 15;

    int q0 = blockIdx.x * 64;
    int h  = blockIdx.y;
    int b  = blockIdx.z;

    const float* Qb = Q  + ((size_t)(b * SS + q0)) * DD + h * DK;
    const float* Kb = Kk + ((size_t)b * SS) * DD + h * DK;
    const float* Vb = V  + ((size_t)b * SS) * DD + h * DK;
    const int*   mb = mask + b * SS;

    int sr = tid >> 2, dbase = (tid & 3) * 16;
    int s_jn = sr >> 3, s_g = sr & 7;
    int s_ks = sr >> 3, s_tq = sr & 3, s_reg = (sr >> 2) & 1;
    int q_im = sr >> 4, q_g = sr & 7, q_half = (sr >> 3) & 1;

    #pragma unroll
    for (int cch = 0; cch < 4; cch++) {
        int d0 = dbase + cch * 4;
        float4 v = *(const float4*)(Qb + (size_t)sr * DD + d0);
        float vv[4] = {v.x, v.y, v.z, v.w};
        #pragma unroll
        for (int e = 0; e < 4; e++) {
            int d = d0 + e;
            int reg = q_half + 2 * ((d >> 2) & 1);
            int ln  = q_g * 4 + (d & 3);
            Qf[(((d >> 3) * 4 + q_im) * 32 + ln) * 4 + reg] = f2tf(vv[e] * 0.125f);
        }
    }

    float acc_o[2][2][4];
    #pragma unroll
    for (int i = 0; i < 2; i++)
        #pragma unroll
        for (int j = 0; j < 2; j++)
            #pragma unroll
            for (int r = 0; r < 4; r++) acc_o[i][j][r] = 0.f;
    float mrow[4], lrow[4];
    #pragma unroll
    for (int i = 0; i < 4; i++) { mrow[i] = -INFINITY; lrow[i] = 0.f; }

    for (int kt = 0; kt < SS / 64; kt++) {
        int k0 = kt * 64;
        __syncthreads();

        #pragma unroll
        for (int cch = 0; cch < 4; cch++) {
            int d0 = dbase + cch * 4;
            float4 kv = *(const float4*)(Kb + (size_t)(k0 + sr) * DD + d0);
            float4 vv = *(const float4*)(Vb + (size_t)(k0 + sr) * DD + d0);
            float ka[4] = {kv.x, kv.y, kv.z, kv.w};
            float va[4] = {vv.x, vv.y, vv.z, vv.w};
            #pragma unroll
            for (int e = 0; e < 4; e++) {
                int d = d0 + e;
                int kreg = (d >> 2) & 1;
                int kln  = s_g * 4 + (d & 3);
                Kf[(((d >> 3) * 8 + s_jn) * 32 + kln) * 2 + kreg] = f2tf(ka[e]);
                int vln = (d & 7) * 4 + s_tq;
                Vf[((s_ks * 8 + (d >> 3)) * 32 + vln) * 2 + s_reg] = f2tf(va[e]);
            }
        }
        if (tid < 64) ms[tid] = mb[k0 + tid];
        __syncthreads();

        float sacc[2][2][4];
        #pragma unroll
        for (int i = 0; i < 2; i++)
            #pragma unroll
            for (int j = 0; j < 2; j++)
                #pragma unroll
                for (int r = 0; r < 4; r++) sacc[i][j][r] = 0.f;
        #pragma unroll
        for (int ks = 0; ks < 8; ks++) {
            uint32_t qa[2][4], kb2[2][2];
            #pragma unroll
            for (int im2 = 0; im2 < 2; im2++)
                *(uint4*)&qa[im2][0] =
                    *(const uint4*)&Qf[((ks * 4 + wm * 2 + im2) * 32 + lane) * 4];
            #pragma unroll
            for (int jn2 = 0; jn2 < 2; jn2++)
                *(uint2*)&kb2[jn2][0] =
                    *(const uint2*)&Kf[((ks * 8 + wn * 2 + jn2) * 32 + lane) * 2];
            #pragma unroll
            for (int im2 = 0; im2 < 2; im2++)
                #pragma unroll
                for (int jn2 = 0; jn2 < 2; jn2++)
                    MMA_TF32(sacc[im2][jn2], qa[im2], kb2[jn2]);
        }
        #pragma unroll
        for (int im2 = 0; im2 < 2; im2++) {
            int row = wm * 32 + im2 * 16 + g;
            #pragma unroll
            for (int jn2 = 0; jn2 < 2; jn2++) {
                int col = wn * 16 + jn2 * 8 + 2 * t;
                Ss[row * 68 + col]           = sacc[im2][jn2][0];
                Ss[row * 68 + col + 1]       = sacc[im2][jn2][1];
                Ss[(row + 8) * 68 + col]     = sacc[im2][jn2][2];
                Ss[(row + 8) * 68 + col + 1] = sacc[im2][jn2][3];
            }
        }
        __syncthreads();

        float s4[4][4];
        #pragma unroll
        for (int i = 0; i < 4; i++) {
            float4 r4 = *(const float4*)&Ss[(ty * 4 + i) * 68 + tx * 4];
            s4[i][0] = r4.x; s4[i][1] = r4.y; s4[i][2] = r4.z; s4[i][3] = r4.w;
        }
        #pragma unroll
        for (int i = 0; i < 4; i++)
            #pragma unroll
            for (int j = 0; j < 4; j++)
                if (ms[tx * 4 + j] == 0) s4[i][j] = -INFINITY;

        float scv[4];
        #pragma unroll
        for (int i = 0; i < 4; i++) {
            float mx = fmaxf(fmaxf(s4[i][0], s4[i][1]), fmaxf(s4[i][2], s4[i][3]));
            #pragma unroll
            for (int off = 8; off; off >>= 1)
                mx = fmaxf(mx, __shfl_xor_sync(0xffffffffu, mx, off));
            float mn = fmaxf(mrow[i], mx);
            float scl = (mrow[i] == -INFINITY) ? 0.f : __expf(mrow[i] - mn);
            float sum = 0.f;
            #pragma unroll
            for (int j = 0; j < 4; j++) {
                float p = __expf(s4[i][j] - mn);
                s4[i][j] = p; sum += p;
            }
            #pragma unroll
            for (int off = 8; off; off >>= 1)
                sum += __shfl_xor_sync(0xffffffffu, sum, off);
            lrow[i] = lrow[i] * scl + sum;
            mrow[i] = mn;
            scv[i] = scl;
        }
        #pragma unroll
        for (int i = 0; i < 4; i++) {
            int row = ty * 4 + i;
            int p_im = row >> 4, p_g = row & 7, p_half = (row >> 3) & 1;
            #pragma unroll
            for (int j = 0; j < 4; j++) {
                int col = tx * 4 + j;
                int reg = p_half + 2 * ((col >> 2) & 1);
                int ln  = p_g * 4 + (col & 3);
                Pf[(((col >> 3) * 4 + p_im) * 32 + ln) * 4 + reg] = f2tf(s4[i][j]);
            }
            if (tx == 0) sc[row] = scv[i];
        }
        __syncthreads();

        #pragma unroll
        for (int im2 = 0; im2 < 2; im2++) {
            int rl = wm * 32 + im2 * 16 + g;
            float s0 = sc[rl], s1 = sc[rl + 8];
            #pragma unroll
            for (int jn2 = 0; jn2 < 2; jn2++) {
                acc_o[im2][jn2][0] *= s0; acc_o[im2][jn2][1] *= s0;
                acc_o[im2][jn2][2] *= s1; acc_o[im2][jn2][3] *= s1;
            }
        }
        #pragma unroll
        for (int ks = 0; ks < 8; ks++) {
            uint32_t pa[2][4], vb2[2][2];
            #pragma unroll
            for (int im2 = 0; im2 < 2; im2++)
                *(uint4*)&pa[im2][0] =
                    *(const uint4*)&Pf[((ks * 4 + wm * 2 + im2) * 32 + lane) * 4];
            #pragma unroll
            for (int jn2 = 0; jn2 < 2; jn2++)
                *(uint2*)&vb2[jn2][0] =
                    *(const uint2*)&Vf[((ks * 8 + wn * 2 + jn2) * 32 + lane) * 2];
            #pragma unroll
            for (int im2 = 0; im2 < 2; im2++)
                #pragma unroll
                for (int jn2 = 0; jn2 < 2; jn2++)
                    MMA_TF32(acc_o[im2][jn2], pa[im2], vb2[jn2]);
        }
    }

    __syncthreads();
    #pragma unroll
    for (int i = 0; i < 4; i++)
        if (tx == 0) li[ty * 4 + i] = 1.0f / lrow[i];
    __syncthreads();

    float* Ob = O + ((size_t)(b * SS + q0)) * DD + h * DK;
    #pragma unroll
    for (int im2 = 0; im2 < 2; im2++) {
        int rl = wm * 32 + im2 * 16 + g;
        float il0 = li[rl], il1 = li[rl + 8];
        #pragma unroll
        for (int jn2 = 0; jn2 < 2; jn2++) {
            int col = wn * 16 + jn2 * 8 + 2 * t;
            *(float2*)(Ob + (size_t)rl * DD + col) =
                make_float2(acc_o[im2][jn2][0] * il0, acc_o[im2][jn2][1] * il0);
            *(float2*)(Ob + (size_t)(rl + 8) * DD + col) =
                make_float2(acc_o[im2][jn2][2] * il1, acc_o[im2][jn2][3] * il1);
        }
    }
}

// ---------------- launch ------------------------------------------------------
extern "C" void kernel_launch(void* const* d_in, const int* in_sizes, int n_in,
                              void* d_out, int out_size)
{
    const float* x    = (const float*)d_in[0];
    const int*   mask = (const int*)  d_in[1];
    const float* wq   = (const float*)d_in[2];
    const float* bq   = (const float*)d_in[3];
    const float* wk   = (const float*)d_in[4];
    const float* bk   = (const float*)d_in[5];
    const float* wv   = (const float*)d_in[6];
    const float* bv   = (const float*)d_in[7];
    const float* wo   = (const float*)d_in[8];
    const float* bo   = (const float*)d_in[9];
    const float* w1   = (const float*)d_in[10];
    const float* b1   = (const float*)d_in[11];
    const float* w2   = (const float*)d_in[12];
    const float* b2   = (const float*)d_in[13];
    const float* ln1w = (const float*)d_in[14];
    const float* ln1b = (const float*)d_in[15];
    const float* ln2w = (const float*)d_in[16];
    const float* ln2b = (const float*)d_in[17];
    float* out = (float*)d_out;

    float *xn, *q, *k, *v, *attn, *x1, *hb;
    uint32_t* wf;
    cudaGetSymbolAddress((void**)&xn,   g_xn);
    cudaGetSymbolAddress((void**)&q,    g_q);
    cudaGetSymbolAddress((void**)&k,    g_k);
    cudaGetSymbolAddress((void**)&v,    g_v);
    cudaGetSymbolAddress((void**)&attn, g_attn);
    cudaGetSymbolAddress((void**)&x1,   g_x1);
    cudaGetSymbolAddress((void**)&hb,   g_h);
    cudaGetSymbolAddress((void**)&wf,   g_wf);

    cudaFuncSetAttribute(flash_kernel,
                         cudaFuncAttributeMaxDynamicSharedMemorySize,
                         F_TOT * (int)sizeof(uint32_t));

    dim3 gD  (DD  / 128, NROW / 128);
    dim3 gQKV(DD  / 128, NROW / 128, 3);
    dim3 gF  (DFF / 128, NROW / 128);
    dim3 gAtt(SS / 64, HH, BB);

    // 0) weight fragment pre-layout
    wlayout_kernel<<<dim3(DD  / 8, DD  / 8), 64>>>(wq, wf + WF_Q, DD);
    wlayout_kernel<<<dim3(DD  / 8, DD  / 8), 64>>>(wk, wf + WF_K, DD);
    wlayout_kernel<<<dim3(DD  / 8, DD  / 8), 64>>>(wv, wf + WF_V, DD);
    wlayout_kernel<<<dim3(DD  / 8, DD  / 8), 64>>>(wo, wf + WF_O, DD);
    wlayout_kernel<<<dim3(DFF / 8, DD  / 8), 64>>>(w1, wf + WF_1, DFF);
    wlayout_kernel<<<dim3(DD  / 8, DFF / 8), 64>>>(w2, wf + WF_2, DD);

    // 1) ln1
    ln_kernel<<<NROW, 256>>>(x, ln1w, ln1b, xn);
    // 2) fused QKV
    qkv_kernel<<<gQKV, 256>>>(xn, wf, bq, bk, bv, q, k, v);
    // 3) attention
    flash_kernel<<<gAtt, 256, F_TOT * sizeof(uint32_t)>>>(q, k, v, mask, attn);
    // 4) output projection + residual
    tgemm_kernel<2><<<gD, 256>>>(attn, wf + WF_O, bo, x, x1, DD, DD);
    // 5) ln2
    ln_kernel<<<NROW, 256>>>(x1, ln2w, ln2b, xn);
    // 6) FFN up + relu
    tgemm_kernel<1><<<gF, 256>>>(xn, wf + WF_1, b1, nullptr, hb, DD, DFF);
    // 7) FFN down + residual -> out
    tgemm_kernel<2><<<gD, 256>>>(hb, wf + WF_2, b2, x1, out, DFF, DD);
}

// round 7
// speedup vs baseline: 2.1048x; 1.0902x over previous
#include <cuda_runtime.h>
#include <math.h>
#include <stdint.h>

// Problem dims (fixed by reference)
#define BB   4
#define SS   2048
#define DD   1024
#define HH   16
#define DK   64
#define DFF  4096
#define NROW (BB*SS)          // 8192
#define LEPS 1e-6f

// ---------------- scratch (static __device__, no allocations) ----------------
__device__ float g_xn  [(size_t)NROW * DD];
__device__ float g_q   [(size_t)NROW * DD];
__device__ float g_k   [(size_t)NROW * DD];
__device__ float g_v   [(size_t)NROW * DD];
__device__ float g_attn[(size_t)NROW * DD];
__device__ float g_x1  [(size_t)NROW * DD];
__device__ float g_h   [(size_t)NROW * DFF];
// pre-laid tf32 weight fragments: wq,wk,wv,wo (1M each), w1 (4M), w2 (4M)
__device__ uint32_t g_wf[(size_t)13 * 1024 * 1024];

#define WF_Q  ((size_t)0)
#define WF_K  ((size_t)1  * 1024 * 1024)
#define WF_V  ((size_t)2  * 1024 * 1024)
#define WF_O  ((size_t)3  * 1024 * 1024)
#define WF_1  ((size_t)4  * 1024 * 1024)
#define WF_2  ((size_t)8  * 1024 * 1024)

// ---------------- helpers -----------------------------------------------------
__device__ __forceinline__ uint32_t f2tf(float f) {
    uint32_t u;
    asm("cvt.rna.tf32.f32 %0, %1;" : "=r"(u) : "f"(f));
    return u;
}

#define MMA_TF32(d, a, b)                                                     \
    asm volatile("mma.sync.aligned.m16n8k8.row.col.f32.tf32.tf32.f32 "        \
                 "{%0,%1,%2,%3},{%4,%5,%6,%7},{%8,%9},{%0,%1,%2,%3};"         \
                 : "+f"(d[0]), "+f"(d[1]), "+f"(d[2]), "+f"(d[3])             \
                 : "r"(a[0]), "r"(a[1]), "r"(a[2]), "r"(a[3]),                \
                   "r"(b[0]), "r"(b[1]))

#define LDSM_X4(r0, r1, r2, r3, addr)                                         \
    asm volatile("ldmatrix.sync.aligned.m8n8.x4.shared.b16 {%0,%1,%2,%3}, [%4];" \
                 : "=r"(r0), "=r"(r1), "=r"(r2), "=r"(r3) : "r"(addr))

#define CP_ASYNC16(dst, src)                                                  \
    asm volatile("cp.async.ca.shared.global [%0], [%1], 16;"                  \
                 :: "r"(dst), "l"(src))
#define CP_COMMIT() asm volatile("cp.async.commit_group;")
#define CP_WAIT(n)  asm volatile("cp.async.wait_group %0;" :: "n"(n))

// ---------------- weight fragment pre-layout (MLP=4) ---------------------------
// Wf[kb][mb][lane*2+reg] = tf32( W[kb*8 + (lane&3) + reg*4][mb*8 + (lane>>2)] )
__global__ void wlayout_kernel(const float* __restrict__ W,
                               uint32_t* __restrict__ Wf, int M)
{
    int mb = blockIdx.x;
    int kb0 = blockIdx.y * 4;
    int tid = threadIdx.x;                 // 64 threads
    int lane = tid & 31, reg = tid >> 5;
    int t = lane & 3, g = lane >> 2;
    #pragma unroll
    for (int i = 0; i < 4; i++) {
        int kb = kb0 + i;
        float v = W[(size_t)(kb * 8 + t + reg * 4) * M + mb * 8 + g];
        Wf[(((size_t)kb * (M >> 3)) + mb) * 64 + lane * 2 + reg] = f2tf(v);
    }
}

// ---------------- LayerNorm (ddof=1, divide by std+eps) ----------------------
__global__ void ln_kernel(const float* __restrict__ x,
                          const float* __restrict__ w,
                          const float* __restrict__ b,
                          float* __restrict__ y)
{
    int row = blockIdx.x;
    const float* xr = x + (size_t)row * DD;
    int c = threadIdx.x * 4;
    float4 v = *(const float4*)(xr + c);
    float s  = v.x + v.y + v.z + v.w;
    float sq = v.x*v.x + v.y*v.y + v.z*v.z + v.w*v.w;
    #pragma unroll
    for (int o = 16; o; o >>= 1) {
        s  += __shfl_xor_sync(0xffffffffu, s,  o);
        sq += __shfl_xor_sync(0xffffffffu, sq, o);
    }
    __shared__ float ssm[8], sqm[8];
    int wid = threadIdx.x >> 5, lid = threadIdx.x & 31;
    if (lid == 0) { ssm[wid] = s; sqm[wid] = sq; }
    __syncthreads();
    if (wid == 0) {
        float a = (lid < 8) ? ssm[lid] : 0.f;
        float q = (lid < 8) ? sqm[lid] : 0.f;
        #pragma unroll
        for (int o = 16; o; o >>= 1) {
            a += __shfl_xor_sync(0xffffffffu, a, o);
            q += __shfl_xor_sync(0xffffffffu, q, o);
        }
        if (lid == 0) { ssm[0] = a; sqm[0] = q; }
    }
    __syncthreads();
    float sum = ssm[0], sumsq = sqm[0];
    float mean = sum * (1.0f / DD);
    float var  = (sumsq - sum * mean) * (1.0f / (DD - 1));
    float inv  = 1.0f / (sqrtf(var) + LEPS);

    float4 wv = *(const float4*)(w + c);
    float4 bv = *(const float4*)(b + c);
    float4 out;
    out.x = wv.x * (v.x - mean) * inv + bv.x;
    out.y = wv.y * (v.y - mean) * inv + bv.y;
    out.z = wv.z * (v.z - mean) * inv + bv.z;
    out.w = wv.w * (v.w - mean) * inv + bv.w;
    *(float4*)(y + (size_t)row * DD + c) = out;
}

// ---------------- TF32 GEMM: 4-stage cp.async pipeline ------------------------
// C[N,M] = A[N,K] @ W[K,M] + bias (+relu / +resid)
// 128x128 tile, BK=16, 8 warps (2x4), warp tile 64x32.
// A staged raw fp32 (tf32 truncation at MMA), B pre-laid fragments in gmem.
#define STAGES    4
#define AS_WORDS  2560                      // 128 rows x 20 (pad) words
#define BS_WORDS  2048                      // 2ks x 16jn x 32lane x 2reg
#define STG_WORDS (AS_WORDS + BS_WORDS)     // 4608
#define GSMEM_BYTES (STAGES * STG_WORDS * 4)  // 73728

template<int MODE>
__device__ __forceinline__
void tgemm_body(const float* __restrict__ A, const uint32_t* __restrict__ Wf,
                const float* __restrict__ bias, const float* __restrict__ resid,
                float* __restrict__ C, int K, int M, int bx, int by)
{
    extern __shared__ __align__(16) uint32_t dsm[];

    int tid  = threadIdx.x;
    int lane = tid & 31, warp = tid >> 5;
    int wm = warp >> 2, wn = warp & 3;
    int g = lane >> 2, t = lane & 3;
    int row0 = by * 128, col0 = bx * 128;
    const int MB = M >> 3;
    const int KT = K >> 4;

    // A staging: thread -> row ar, k-half aks (8 floats = 2 x 16B cp.async)
    int ar = tid >> 1, aks = tid & 1;
    const float* Aptr = A + (size_t)(row0 + ar) * K + aks * 8;

    // B staging: contiguous copy (8 u32 = 2 x 16B cp.async)
    int bks = tid >> 7;
    int bidx = (tid & 127) * 8;
    const uint32_t* Wfp = Wf + ((size_t)bks * MB + (col0 >> 3)) * 64 + bidx;
    const size_t wstep = (size_t)2 * MB * 64;

    uint32_t smem_u32 = (uint32_t)__cvta_generic_to_shared(dsm);
    uint32_t a_dst = smem_u32 + (uint32_t)(ar * 20 + aks * 8) * 4;
    uint32_t b_dst = smem_u32 + (uint32_t)(AS_WORDS + bks * 1024 + bidx) * 4;

    // ldmatrix address pieces
    int lm_tile = lane >> 3, lm_r = lane & 7;
    int lm_row_base = wm * 64 + (lm_tile & 1) * 8 + lm_r;
    int lm_colw = (lm_tile >> 1) * 4;

    float acc[4][4][4];
    #pragma unroll
    for (int i = 0; i < 4; i++)
        #pragma unroll
        for (int j = 0; j < 4; j++)
            #pragma unroll
            for (int r = 0; r < 4; r++) acc[i][j][r] = 0.f;

    // ---- prologue: stages 0..STAGES-2 ----
    #pragma unroll
    for (int s = 0; s < STAGES - 1; s++) {
        uint32_t soff = (uint32_t)(s * STG_WORDS) * 4;
        const float* asrc = Aptr + s * 16;
        CP_ASYNC16(a_dst + soff,      asrc);
        CP_ASYNC16(a_dst + soff + 16, asrc + 4);
        const uint32_t* bsrc = Wfp + (size_t)s * wstep;
        CP_ASYNC16(b_dst + soff,      bsrc);
        CP_ASYNC16(b_dst + soff + 16, bsrc + 4);
        CP_COMMIT();
    }

    for (int kt = 0; kt < KT; kt++) {
        CP_WAIT(STAGES - 2);
        __syncthreads();

        int pf = kt + STAGES - 1;
        if (pf < KT) {
            uint32_t soff = (uint32_t)((pf & (STAGES - 1)) * STG_WORDS) * 4;
            const float* asrc = Aptr + pf * 16;
            CP_ASYNC16(a_dst + soff,      asrc);
            CP_ASYNC16(a_dst + soff + 16, asrc + 4);
            const uint32_t* bsrc = Wfp + (size_t)pf * wstep;
            CP_ASYNC16(b_dst + soff,      bsrc);
            CP_ASYNC16(b_dst + soff + 16, bsrc + 4);
        }
        CP_COMMIT();

        int cs = kt & (STAGES - 1);
        uint32_t as_base = smem_u32 + (uint32_t)(cs * STG_WORDS) * 4;
        const uint32_t* BfS = dsm + cs * STG_WORDS + AS_WORDS;

        #pragma unroll
        for (int ks = 0; ks < 2; ks++) {
            uint32_t afr[4][4], bfr[4][2];
            #pragma unroll
            for (int im = 0; im < 4; im++) {
                int row = lm_row_base + im * 16;
                uint32_t addr = as_base + (uint32_t)(row * 20 + ks * 8 + lm_colw) * 4u;
                LDSM_X4(afr[im][0], afr[im][1], afr[im][2], afr[im][3], addr);
            }
            #pragma unroll
            for (int jn = 0; jn < 4; jn++)
                *(uint2*)&bfr[jn][0] =
                    *(const uint2*)&BfS[ks * 1024 + (wn * 4 + jn) * 64 + lane * 2];
            #pragma unroll
            for (int im = 0; im < 4; im++)
                #pragma unroll
                for (int jn = 0; jn < 4; jn++)
                    MMA_TF32(acc[im][jn], afr[im], bfr[jn]);
        }
    }

    // epilogue (fragment: c0,c1 = row g cols 2t,2t+1; c2,c3 = row g+8)
    #pragma unroll
    for (int im = 0; im < 4; im++) {
        int rA = row0 + wm * 64 + im * 16 + g;
        int rB = rA + 8;
        #pragma unroll
        for (int jn = 0; jn < 4; jn++) {
            int col = col0 + wn * 32 + jn * 8 + 2 * t;
            float bx0 = bias[col], bx1 = bias[col + 1];
            float v0 = acc[im][jn][0] + bx0;
            float v1 = acc[im][jn][1] + bx1;
            float v2 = acc[im][jn][2] + bx0;
            float v3 = acc[im][jn][3] + bx1;
            if (MODE == 1) {
                v0 = fmaxf(v0, 0.f); v1 = fmaxf(v1, 0.f);
                v2 = fmaxf(v2, 0.f); v3 = fmaxf(v3, 0.f);
            }
            size_t oA = (size_t)rA * M + col;
            size_t oB = (size_t)rB * M + col;
            if (MODE == 2) {
                float2 r0 = *(const float2*)(resid + oA);
                float2 r1 = *(const float2*)(resid + oB);
                v0 += r0.x; v1 += r0.y; v2 += r1.x; v3 += r1.y;
            }
            *(float2*)(C + oA) = make_float2(v0, v1);
            *(float2*)(C + oB) = make_float2(v2, v3);
        }
    }
}

template<int MODE>
__global__ __launch_bounds__(256, 2)
void tgemm_kernel(const float* __restrict__ A, const uint32_t* __restrict__ Wf,
                  const float* __restrict__ bias, const float* __restrict__ resid,
                  float* __restrict__ C, int K, int M)
{
    tgemm_body<MODE>(A, Wf, bias, resid, C, K, M, blockIdx.x, blockIdx.y);
}

__global__ __launch_bounds__(256, 2)
void qkv_kernel(const float* __restrict__ A, const uint32_t* __restrict__ wf,
                const float* __restrict__ bq, const float* __restrict__ bk,
                const float* __restrict__ bv,
                float* __restrict__ q, float* __restrict__ k, float* __restrict__ v)
{
    const uint32_t* W; const float* bias; float* C;
    if (blockIdx.z == 0)      { W = wf + WF_Q; bias = bq; C = q; }
    else if (blockIdx.z == 1) { W = wf + WF_K; bias = bk; C = k; }
    else                      { W = wf + WF_V; bias = bv; C = v; }
    tgemm_body<0>(A, W, bias, nullptr, C, DD, DD, blockIdx.x, blockIdx.y);
}

// ---------------- Tensorized flash attention ----------------------------------
#define F_QF 0
#define F_KF 4096
#define F_VF 8192
#define F_PF 12288
#define F_SS 16384
#define F_SC 20736
#define F_LI 20800
#define F_MS 20864
#define F_TOT 20928

__global__ __launch_bounds__(256)
void flash_kernel(const float* __restrict__ Q, const float* __restrict__ Kk,
                  const float* __restrict__ V, const int* __restrict__ mask,
                  float* __restrict__ O)
{
    extern __shared__ __align__(16) uint32_t smu[];
    uint32_t* Qf = smu + F_QF;
    uint32_t* Kf = smu + F_KF;
    uint32_t* Vf = smu + F_VF;
    uint32_t* Pf = smu + F_PF;
    float*    Ss = (float*)(smu + F_SS);
    float*    sc = (float*)(smu + F_SC);
    float*    li = (float*)(smu + F_LI);
    int*      ms = (int*)  (smu + F_MS);

    int tid  = threadIdx.x;
    int lane = tid & 31, warp = tid >> 5;
    int wm = warp >> 2, wn = warp & 3;
    int g = lane >> 2, t = lane & 3;
    int ty = tid >> 4, tx = tid & 15;

    int q0 = blockIdx.x * 64;
    int h  = blockIdx.y;
    int b  = blockIdx.z;

    const float* Qb = Q  + ((size_t)(b * SS + q0)) * DD + h * DK;
    const float* Kb = Kk + ((size_t)b * SS) * DD + h * DK;
    const float* Vb = V  + ((size_t)b * SS) * DD + h * DK;
    const int*   mb = mask + b * SS;

    int sr = tid >> 2, dbase = (tid & 3) * 16;
    int s_jn = sr >> 3, s_g = sr & 7;
    int s_ks = sr >> 3, s_tq = sr & 3, s_reg = (sr >> 2) & 1;
    int q_im = sr >> 4, q_g = sr & 7, q_half = (sr >> 3) & 1;

    #pragma unroll
    for (int cch = 0; cch < 4; cch++) {
        int d0 = dbase + cch * 4;
        float4 v = *(const float4*)(Qb + (size_t)sr * DD + d0);
        float vv[4] = {v.x, v.y, v.z, v.w};
        #pragma unroll
        for (int e = 0; e < 4; e++) {
            int d = d0 + e;
            int reg = q_half + 2 * ((d >> 2) & 1);
            int ln  = q_g * 4 + (d & 3);
            Qf[(((d >> 3) * 4 + q_im) * 32 + ln) * 4 + reg] =
                __float_as_uint(vv[e] * 0.125f);
        }
    }

    float acc_o[2][2][4];
    #pragma unroll
    for (int i = 0; i < 2; i++)
        #pragma unroll
        for (int j = 0; j < 2; j++)
            #pragma unroll
            for (int r = 0; r < 4; r++) acc_o[i][j][r] = 0.f;
    float mrow[4], lrow[4];
    #pragma unroll
    for (int i = 0; i < 4; i++) { mrow[i] = -INFINITY; lrow[i] = 0.f; }

    for (int kt = 0; kt < SS / 64; kt++) {
        int k0 = kt * 64;
        __syncthreads();

        #pragma unroll
        for (int cch = 0; cch < 4; cch++) {
            int d0 = dbase + cch * 4;
            float4 kv = *(const float4*)(Kb + (size_t)(k0 + sr) * DD + d0);
            float4 vv = *(const float4*)(Vb + (size_t)(k0 + sr) * DD + d0);
            float ka[4] = {kv.x, kv.y, kv.z, kv.w};
            float va[4] = {vv.x, vv.y, vv.z, vv.w};
            #pragma unroll
            for (int e = 0; e < 4; e++) {
                int d = d0 + e;
                int kreg = (d >> 2) & 1;
                int kln  = s_g * 4 + (d & 3);
                Kf[(((d >> 3) * 8 + s_jn) * 32 + kln) * 2 + kreg] =
                    __float_as_uint(ka[e]);
                int vln = (d & 7) * 4 + s_tq;
                Vf[((s_ks * 8 + (d >> 3)) * 32 + vln) * 2 + s_reg] =
                    __float_as_uint(va[e]);
            }
        }
        if (tid < 64) ms[tid] = mb[k0 + tid];
        __syncthreads();

        float sacc[2][2][4];
        #pragma unroll
        for (int i = 0; i < 2; i++)
            #pragma unroll
            for (int j = 0; j < 2; j++)
                #pragma unroll
                for (int r = 0; r < 4; r++) sacc[i][j][r] = 0.f;
        #pragma unroll
        for (int ks = 0; ks < 8; ks++) {
            uint32_t qa[2][4], kb2[2][2];
            #pragma unroll
            for (int im2 = 0; im2 < 2; im2++)
                *(uint4*)&qa[im2][0] =
                    *(const uint4*)&Qf[((ks * 4 + wm * 2 + im2) * 32 + lane) * 4];
            #pragma unroll
            for (int jn2 = 0; jn2 < 2; jn2++)
                *(uint2*)&kb2[jn2][0] =
                    *(const uint2*)&Kf[((ks * 8 + wn * 2 + jn2) * 32 + lane) * 2];
            #pragma unroll
            for (int im2 = 0; im2 < 2; im2++)
                #pragma unroll
                for (int jn2 = 0; jn2 < 2; jn2++)
                    MMA_TF32(sacc[im2][jn2], qa[im2], kb2[jn2]);
        }
        #pragma unroll
        for (int im2 = 0; im2 < 2; im2++) {
            int row = wm * 32 + im2 * 16 + g;
            #pragma unroll
            for (int jn2 = 0; jn2 < 2; jn2++) {
                int col = wn * 16 + jn2 * 8 + 2 * t;
                Ss[row * 68 + col]           = sacc[im2][jn2][0];
                Ss[row * 68 + col + 1]       = sacc[im2][jn2][1];
                Ss[(row + 8) * 68 + col]     = sacc[im2][jn2][2];
                Ss[(row + 8) * 68 + col + 1] = sacc[im2][jn2][3];
            }
        }
        __syncthreads();

        float s4[4][4];
        #pragma unroll
        for (int i = 0; i < 4; i++) {
            float4 r4 = *(const float4*)&Ss[(ty * 4 + i) * 68 + tx * 4];
            s4[i][0] = r4.x; s4[i][1] = r4.y; s4[i][2] = r4.z; s4[i][3] = r4.w;
        }
        #pragma unroll
        for (int i = 0; i < 4; i++)
            #pragma unroll
            for (int j = 0; j < 4; j++)
                if (ms[tx * 4 + j] == 0) s4[i][j] = -INFINITY;

        float scv[4];
        #pragma unroll
        for (int i = 0; i < 4; i++) {
            float mx = fmaxf(fmaxf(s4[i][0], s4[i][1]), fmaxf(s4[i][2], s4[i][3]));
            #pragma unroll
            for (int off = 8; off; off >>= 1)
                mx = fmaxf(mx, __shfl_xor_sync(0xffffffffu, mx, off));
            float mn = fmaxf(mrow[i], mx);
            float scl = (mrow[i] == -INFINITY) ? 0.f : __expf(mrow[i] - mn);
            float sum = 0.f;
            #pragma unroll
            for (int j = 0; j < 4; j++) {
                float p = __expf(s4[i][j] - mn);
                s4[i][j] = p; sum += p;
            }
            #pragma unroll
            for (int off = 8; off; off >>= 1)
                sum += __shfl_xor_sync(0xffffffffu, sum, off);
            lrow[i] = lrow[i] * scl + sum;
            mrow[i] = mn;
            scv[i] = scl;
        }
        #pragma unroll
        for (int i = 0; i < 4; i++) {
            int row = ty * 4 + i;
            int p_im = row >> 4, p_g = row & 7, p_half = (row >> 3) & 1;
            #pragma unroll
            for (int j = 0; j < 4; j++) {
                int col = tx * 4 + j;
                int reg = p_half + 2 * ((col >> 2) & 1);
                int ln  = p_g * 4 + (col & 3);
                Pf[(((col >> 3) * 4 + p_im) * 32 + ln) * 4 + reg] =
                    __float_as_uint(s4[i][j]);
            }
            if (tx == 0) sc[row] = scv[i];
        }
        __syncthreads();

        #pragma unroll
        for (int im2 = 0; im2 < 2; im2++) {
            int rl = wm * 32 + im2 * 16 + g;
            float s0 = sc[rl], s1 = sc[rl + 8];
            #pragma unroll
            for (int jn2 = 0; jn2 < 2; jn2++) {
                acc_o[im2][jn2][0] *= s0; acc_o[im2][jn2][1] *= s0;
                acc_o[im2][jn2][2] *= s1; acc_o[im2][jn2][3] *= s1;
            }
        }
        #pragma unroll
        for (int ks = 0; ks < 8; ks++) {
            uint32_t pa[2][4], vb2[2][2];
            #pragma unroll
            for (int im2 = 0; im2 < 2; im2++)
                *(uint4*)&pa[im2][0] =
                    *(const uint4*)&Pf[((ks * 4 + wm * 2 + im2) * 32 + lane) * 4];
            #pragma unroll
            for (int jn2 = 0; jn2 < 2; jn2++)
                *(uint2*)&vb2[jn2][0] =
                    *(const uint2*)&Vf[((ks * 8 + wn * 2 + jn2) * 32 + lane) * 2];
            #pragma unroll
            for (int im2 = 0; im2 < 2; im2++)
                #pragma unroll
                for (int jn2 = 0; jn2 < 2; jn2++)
                    MMA_TF32(acc_o[im2][jn2], pa[im2], vb2[jn2]);
        }
    }

    __syncthreads();
    #pragma unroll
    for (int i = 0; i < 4; i++)
        if (tx == 0) li[ty * 4 + i] = 1.0f / lrow[i];
    __syncthreads();

    float* Ob = O + ((size_t)(b * SS + q0)) * DD + h * DK;
    #pragma unroll
    for (int im2 = 0; im2 < 2; im2++) {
        int rl = wm * 32 + im2 * 16 + g;
        float il0 = li[rl], il1 = li[rl + 8];
        #pragma unroll
        for (int jn2 = 0; jn2 < 2; jn2++) {
            int col = wn * 16 + jn2 * 8 + 2 * t;
            *(float2*)(Ob + (size_t)rl * DD + col) =
                make_float2(acc_o[im2][jn2][0] * il0, acc_o[im2][jn2][1] * il0);
            *(float2*)(Ob + (size_t)(rl + 8) * DD + col) =
                make_float2(acc_o[im2][jn2][2] * il1, acc_o[im2][jn2][3] * il1);
        }
    }
}

// ---------------- launch ------------------------------------------------------
extern "C" void kernel_launch(void* const* d_in, const int* in_sizes, int n_in,
                              void* d_out, int out_size)
{
    const float* x    = (const float*)d_in[0];
    const int*   mask = (const int*)  d_in[1];
    const float* wq   = (const float*)d_in[2];
    const float* bq   = (const float*)d_in[3];
    const float* wk   = (const float*)d_in[4];
    const float* bk   = (const float*)d_in[5];
    const float* wv   = (const float*)d_in[6];
    const float* bv   = (const float*)d_in[7];
    const float* wo   = (const float*)d_in[8];
    const float* bo   = (const float*)d_in[9];
    const float* w1   = (const float*)d_in[10];
    const float* b1   = (const float*)d_in[11];
    const float* w2   = (const float*)d_in[12];
    const float* b2   = (const float*)d_in[13];
    const float* ln1w = (const float*)d_in[14];
    const float* ln1b = (const float*)d_in[15];
    const float* ln2w = (const float*)d_in[16];
    const float* ln2b = (const float*)d_in[17];
    float* out = (float*)d_out;

    float *xn, *q, *k, *v, *attn, *x1, *hb;
    uint32_t* wf;
    cudaGetSymbolAddress((void**)&xn,   g_xn);
    cudaGetSymbolAddress((void**)&q,    g_q);
    cudaGetSymbolAddress((void**)&k,    g_k);
    cudaGetSymbolAddress((void**)&v,    g_v);
    cudaGetSymbolAddress((void**)&attn, g_attn);
    cudaGetSymbolAddress((void**)&x1,   g_x1);
    cudaGetSymbolAddress((void**)&hb,   g_h);
    cudaGetSymbolAddress((void**)&wf,   g_wf);

    cudaFuncSetAttribute(flash_kernel,
                         cudaFuncAttributeMaxDynamicSharedMemorySize,
                         F_TOT * (int)sizeof(uint32_t));
    cudaFuncSetAttribute(tgemm_kernel<1>,
                         cudaFuncAttributeMaxDynamicSharedMemorySize, GSMEM_BYTES);
    cudaFuncSetAttribute(tgemm_kernel<2>,
                         cudaFuncAttributeMaxDynamicSharedMemorySize, GSMEM_BYTES);
    cudaFuncSetAttribute(qkv_kernel,
                         cudaFuncAttributeMaxDynamicSharedMemorySize, GSMEM_BYTES);

    dim3 gD  (DD  / 128, NROW / 128);
    dim3 gQKV(DD  / 128, NROW / 128, 3);
    dim3 gF  (DFF / 128, NROW / 128);
    dim3 gAtt(SS / 64, HH, BB);

    // 0) weight fragment pre-layout
    wlayout_kernel<<<dim3(DD  / 8, DD  / 32), 64>>>(wq, wf + WF_Q, DD);
    wlayout_kernel<<<dim3(DD  / 8, DD  / 32), 64>>>(wk, wf + WF_K, DD);
    wlayout_kernel<<<dim3(DD  / 8, DD  / 32), 64>>>(wv, wf + WF_V, DD);
    wlayout_kernel<<<dim3(DD  / 8, DD  / 32), 64>>>(wo, wf + WF_O, DD);
    wlayout_kernel<<<dim3(DFF / 8, DD  / 32), 64>>>(w1, wf + WF_1, DFF);
    wlayout_kernel<<<dim3(DD  / 8, DFF / 32), 64>>>(w2, wf + WF_2, DD);

    // 1) ln1
    ln_kernel<<<NROW, 256>>>(x, ln1w, ln1b, xn);
    // 2) fused QKV
    qkv_kernel<<<gQKV, 256, GSMEM_BYTES>>>(xn, wf, bq, bk, bv, q, k, v);
    // 3) attention
    flash_kernel<<<gAtt, 256, F_TOT * sizeof(uint32_t)>>>(q, k, v, mask, attn);
    // 4) output projection + residual
    tgemm_kernel<2><<<gD, 256, GSMEM_BYTES>>>(attn, wf + WF_O, bo, x, x1, DD, DD);
    // 5) ln2
    ln_kernel<<<NROW, 256>>>(x1, ln2w, ln2b, xn);
    // 6) FFN up + relu
    tgemm_kernel<1><<<gF, 256, GSMEM_BYTES>>>(xn, wf + WF_1, b1, nullptr, hb, DD, DFF);
    // 7) FFN down + residual -> out
    tgemm_kernel<2><<<gD, 256, GSMEM_BYTES>>>(hb, wf + WF_2, b2, x1, out, DFF, DD);
}

// round 8
// speedup vs baseline: 2.4907x; 1.1833x over previous
#include <cuda_runtime.h>
#include <math.h>
#include <stdint.h>

// Problem dims (fixed by reference)
#define BB   4
#define SS   2048
#define DD   1024
#define HH   16
#define DK   64
#define DFF  4096
#define NROW (BB*SS)          // 8192
#define LEPS 1e-6f

// ---------------- scratch (static __device__, no allocations) ----------------
__device__ float g_xn  [(size_t)NROW * DD];
__device__ float g_q   [(size_t)NROW * DD];
__device__ float g_k   [(size_t)NROW * DD];
__device__ float g_v   [(size_t)NROW * DD];
__device__ float g_attn[(size_t)NROW * DD];
__device__ float g_x1  [(size_t)NROW * DD];
__device__ float g_h   [(size_t)NROW * DFF];
// pre-laid tf32 weight fragments: wq,wk,wv,wo (1M each), w1 (4M), w2 (4M)
__device__ uint32_t g_wf[(size_t)13 * 1024 * 1024];

#define WF_Q  ((size_t)0)
#define WF_K  ((size_t)1  * 1024 * 1024)
#define WF_V  ((size_t)2  * 1024 * 1024)
#define WF_O  ((size_t)3  * 1024 * 1024)
#define WF_1  ((size_t)4  * 1024 * 1024)
#define WF_2  ((size_t)8  * 1024 * 1024)

// ---------------- helpers -----------------------------------------------------
__device__ __forceinline__ uint32_t f2tf(float f) {
    uint32_t u;
    asm("cvt.rna.tf32.f32 %0, %1;" : "=r"(u) : "f"(f));
    return u;
}

#define MMA_TF32(d, a, b)                                                     \
    asm volatile("mma.sync.aligned.m16n8k8.row.col.f32.tf32.tf32.f32 "        \
                 "{%0,%1,%2,%3},{%4,%5,%6,%7},{%8,%9},{%0,%1,%2,%3};"         \
                 : "+f"(d[0]), "+f"(d[1]), "+f"(d[2]), "+f"(d[3])             \
                 : "r"(a[0]), "r"(a[1]), "r"(a[2]), "r"(a[3]),                \
                   "r"(b[0]), "r"(b[1]))

#define LDSM_X4(r0, r1, r2, r3, addr)                                         \
    asm volatile("ldmatrix.sync.aligned.m8n8.x4.shared.b16 {%0,%1,%2,%3}, [%4];" \
                 : "=r"(r0), "=r"(r1), "=r"(r2), "=r"(r3) : "r"(addr))

#define CP_ASYNC16(dst, src)                                                  \
    asm volatile("cp.async.ca.shared.global [%0], [%1], 16;"                  \
                 :: "r"(dst), "l"(src))
#define CP_COMMIT() asm volatile("cp.async.commit_group;")
#define CP_WAIT(n)  asm volatile("cp.async.wait_group %0;" :: "n"(n))

// ---------------- weight fragment pre-layout (MLP=4) ---------------------------
__global__ void wlayout_kernel(const float* __restrict__ W,
                               uint32_t* __restrict__ Wf, int M)
{
    int mb = blockIdx.x;
    int kb0 = blockIdx.y * 4;
    int tid = threadIdx.x;                 // 64 threads
    int lane = tid & 31, reg = tid >> 5;
    int t = lane & 3, g = lane >> 2;
    #pragma unroll
    for (int i = 0; i < 4; i++) {
        int kb = kb0 + i;
        float v = W[(size_t)(kb * 8 + t + reg * 4) * M + mb * 8 + g];
        Wf[(((size_t)kb * (M >> 3)) + mb) * 64 + lane * 2 + reg] = f2tf(v);
    }
}

// ---------------- LayerNorm (ddof=1, divide by std+eps) ----------------------
__global__ void ln_kernel(const float* __restrict__ x,
                          const float* __restrict__ w,
                          const float* __restrict__ b,
                          float* __restrict__ y)
{
    int row = blockIdx.x;
    const float* xr = x + (size_t)row * DD;
    int c = threadIdx.x * 4;
    float4 v = *(const float4*)(xr + c);
    float s  = v.x + v.y + v.z + v.w;
    float sq = v.x*v.x + v.y*v.y + v.z*v.z + v.w*v.w;
    #pragma unroll
    for (int o = 16; o; o >>= 1) {
        s  += __shfl_xor_sync(0xffffffffu, s,  o);
        sq += __shfl_xor_sync(0xffffffffu, sq, o);
    }
    __shared__ float ssm[8], sqm[8];
    int wid = threadIdx.x >> 5, lid = threadIdx.x & 31;
    if (lid == 0) { ssm[wid] = s; sqm[wid] = sq; }
    __syncthreads();
    if (wid == 0) {
        float a = (lid < 8) ? ssm[lid] : 0.f;
        float q = (lid < 8) ? sqm[lid] : 0.f;
        #pragma unroll
        for (int o = 16; o; o >>= 1) {
            a += __shfl_xor_sync(0xffffffffu, a, o);
            q += __shfl_xor_sync(0xffffffffu, q, o);
        }
        if (lid == 0) { ssm[0] = a; sqm[0] = q; }
    }
    __syncthreads();
    float sum = ssm[0], sumsq = sqm[0];
    float mean = sum * (1.0f / DD);
    float var  = (sumsq - sum * mean) * (1.0f / (DD - 1));
    float inv  = 1.0f / (sqrtf(var) + LEPS);

    float4 wv = *(const float4*)(w + c);
    float4 bv = *(const float4*)(b + c);
    float4 out;
    out.x = wv.x * (v.x - mean) * inv + bv.x;
    out.y = wv.y * (v.y - mean) * inv + bv.y;
    out.z = wv.z * (v.z - mean) * inv + bv.z;
    out.w = wv.w * (v.w - mean) * inv + bv.w;
    *(float4*)(y + (size_t)row * DD + c) = out;
}

// ---------------- TF32 GEMM: 4-stage cp.async pipeline (unchanged R7) ---------
#define STAGES    4
#define AS_WORDS  2560
#define BS_WORDS  2048
#define STG_WORDS (AS_WORDS + BS_WORDS)
#define GSMEM_BYTES (STAGES * STG_WORDS * 4)

template<int MODE>
__device__ __forceinline__
void tgemm_body(const float* __restrict__ A, const uint32_t* __restrict__ Wf,
                const float* __restrict__ bias, const float* __restrict__ resid,
                float* __restrict__ C, int K, int M, int bx, int by)
{
    extern __shared__ __align__(16) uint32_t dsm[];

    int tid  = threadIdx.x;
    int lane = tid & 31, warp = tid >> 5;
    int wm = warp >> 2, wn = warp & 3;
    int g = lane >> 2, t = lane & 3;
    int row0 = by * 128, col0 = bx * 128;
    const int MB = M >> 3;
    const int KT = K >> 4;

    int ar = tid >> 1, aks = tid & 1;
    const float* Aptr = A + (size_t)(row0 + ar) * K + aks * 8;

    int bks = tid >> 7;
    int bidx = (tid & 127) * 8;
    const uint32_t* Wfp = Wf + ((size_t)bks * MB + (col0 >> 3)) * 64 + bidx;
    const size_t wstep = (size_t)2 * MB * 64;

    uint32_t smem_u32 = (uint32_t)__cvta_generic_to_shared(dsm);
    uint32_t a_dst = smem_u32 + (uint32_t)(ar * 20 + aks * 8) * 4;
    uint32_t b_dst = smem_u32 + (uint32_t)(AS_WORDS + bks * 1024 + bidx) * 4;

    int lm_tile = lane >> 3, lm_r = lane & 7;
    int lm_row_base = wm * 64 + (lm_tile & 1) * 8 + lm_r;
    int lm_colw = (lm_tile >> 1) * 4;

    float acc[4][4][4];
    #pragma unroll
    for (int i = 0; i < 4; i++)
        #pragma unroll
        for (int j = 0; j < 4; j++)
            #pragma unroll
            for (int r = 0; r < 4; r++) acc[i][j][r] = 0.f;

    #pragma unroll
    for (int s = 0; s < STAGES - 1; s++) {
        uint32_t soff = (uint32_t)(s * STG_WORDS) * 4;
        const float* asrc = Aptr + s * 16;
        CP_ASYNC16(a_dst + soff,      asrc);
        CP_ASYNC16(a_dst + soff + 16, asrc + 4);
        const uint32_t* bsrc = Wfp + (size_t)s * wstep;
        CP_ASYNC16(b_dst + soff,      bsrc);
        CP_ASYNC16(b_dst + soff + 16, bsrc + 4);
        CP_COMMIT();
    }

    for (int kt = 0; kt < KT; kt++) {
        CP_WAIT(STAGES - 2);
        __syncthreads();

        int pf = kt + STAGES - 1;
        if (pf < KT) {
            uint32_t soff = (uint32_t)((pf & (STAGES - 1)) * STG_WORDS) * 4;
            const float* asrc = Aptr + pf * 16;
            CP_ASYNC16(a_dst + soff,      asrc);
            CP_ASYNC16(a_dst + soff + 16, asrc + 4);
            const uint32_t* bsrc = Wfp + (size_t)pf * wstep;
            CP_ASYNC16(b_dst + soff,      bsrc);
            CP_ASYNC16(b_dst + soff + 16, bsrc + 4);
        }
        CP_COMMIT();

        int cs = kt & (STAGES - 1);
        uint32_t as_base = smem_u32 + (uint32_t)(cs * STG_WORDS) * 4;
        const uint32_t* BfS = dsm + cs * STG_WORDS + AS_WORDS;

        #pragma unroll
        for (int ks = 0; ks < 2; ks++) {
            uint32_t afr[4][4], bfr[4][2];
            #pragma unroll
            for (int im = 0; im < 4; im++) {
                int row = lm_row_base + im * 16;
                uint32_t addr = as_base + (uint32_t)(row * 20 + ks * 8 + lm_colw) * 4u;
                LDSM_X4(afr[im][0], afr[im][1], afr[im][2], afr[im][3], addr);
            }
            #pragma unroll
            for (int jn = 0; jn < 4; jn++)
                *(uint2*)&bfr[jn][0] =
                    *(const uint2*)&BfS[ks * 1024 + (wn * 4 + jn) * 64 + lane * 2];
            #pragma unroll
            for (int im = 0; im < 4; im++)
                #pragma unroll
                for (int jn = 0; jn < 4; jn++)
                    MMA_TF32(acc[im][jn], afr[im], bfr[jn]);
        }
    }

    #pragma unroll
    for (int im = 0; im < 4; im++) {
        int rA = row0 + wm * 64 + im * 16 + g;
        int rB = rA + 8;
        #pragma unroll
        for (int jn = 0; jn < 4; jn++) {
            int col = col0 + wn * 32 + jn * 8 + 2 * t;
            float bx0 = bias[col], bx1 = bias[col + 1];
            float v0 = acc[im][jn][0] + bx0;
            float v1 = acc[im][jn][1] + bx1;
            float v2 = acc[im][jn][2] + bx0;
            float v3 = acc[im][jn][3] + bx1;
            if (MODE == 1) {
                v0 = fmaxf(v0, 0.f); v1 = fmaxf(v1, 0.f);
                v2 = fmaxf(v2, 0.f); v3 = fmaxf(v3, 0.f);
            }
            size_t oA = (size_t)rA * M + col;
            size_t oB = (size_t)rB * M + col;
            if (MODE == 2) {
                float2 r0 = *(const float2*)(resid + oA);
                float2 r1 = *(const float2*)(resid + oB);
                v0 += r0.x; v1 += r0.y; v2 += r1.x; v3 += r1.y;
            }
            *(float2*)(C + oA) = make_float2(v0, v1);
            *(float2*)(C + oB) = make_float2(v2, v3);
        }
    }
}

template<int MODE>
__global__ __launch_bounds__(256, 2)
void tgemm_kernel(const float* __restrict__ A, const uint32_t* __restrict__ Wf,
                  const float* __restrict__ bias, const float* __restrict__ resid,
                  float* __restrict__ C, int K, int M)
{
    tgemm_body<MODE>(A, Wf, bias, resid, C, K, M, blockIdx.x, blockIdx.y);
}

__global__ __launch_bounds__(256, 2)
void qkv_kernel(const float* __restrict__ A, const uint32_t* __restrict__ wf,
                const float* __restrict__ bq, const float* __restrict__ bk,
                const float* __restrict__ bv,
                float* __restrict__ q, float* __restrict__ k, float* __restrict__ v)
{
    const uint32_t* W; const float* bias; float* C;
    if (blockIdx.z == 0)      { W = wf + WF_Q; bias = bq; C = q; }
    else if (blockIdx.z == 1) { W = wf + WF_K; bias = bk; C = k; }
    else                      { W = wf + WF_V; bias = bv; C = v; }
    tgemm_body<0>(A, W, bias, nullptr, C, DD, DD, blockIdx.x, blockIdx.y);
}

// ---------------- Tensorized flash attention v2 --------------------------------
// Br=Bc=64, dk=64, 256 threads (8 warps: 2m x 4n).
// Q/K/V staged NATURAL row-major via cp.async (coalesced, no cvt).
// Q,K fragments via ldmatrix.x4; V via conflict-free scalar LDS (pad 72).
// smem word offsets:
#define FL_QS 0            // Q: 64 x 68
#define FL_KS 4352         // K: 64 x 68
#define FL_VS 8704         // V: 64 x 72
#define FL_PF 13312        // P fragments: 4096
#define FL_SS 17408        // S: 64 x 68
#define FL_SC 21760
#define FL_LI 21824
#define FL_MS 21888
#define FL_TOT 21952       // *4 = 87808 bytes

__global__ __launch_bounds__(256)
void flash_kernel(const float* __restrict__ Q, const float* __restrict__ Kk,
                  const float* __restrict__ V, const int* __restrict__ mask,
                  float* __restrict__ O)
{
    extern __shared__ __align__(16) uint32_t smu[];
    float*    Vs = (float*)(smu + FL_VS);
    uint32_t* Pf = smu + FL_PF;
    float*    Ss = (float*)(smu + FL_SS);
    float*    sc = (float*)(smu + FL_SC);
    float*    li = (float*)(smu + FL_LI);
    int*      ms = (int*)  (smu + FL_MS);

    int tid  = threadIdx.x;
    int lane = tid & 31, warp = tid >> 5;
    int wm = warp >> 2, wn = warp & 3;
    int g = lane >> 2, t = lane & 3;
    int ty = tid >> 4, tx = tid & 15;

    int q0 = blockIdx.x * 64;
    int h  = blockIdx.y;
    int b  = blockIdx.z;

    const float* Qb = Q  + ((size_t)(b * SS + q0)) * DD + h * DK;
    const float* Kb = Kk + ((size_t)b * SS) * DD + h * DK;
    const float* Vb = V  + ((size_t)b * SS) * DD + h * DK;
    const int*   mb = mask + b * SS;

    uint32_t smem_b = (uint32_t)__cvta_generic_to_shared(smu);
    uint32_t qs_b = smem_b + FL_QS * 4;
    uint32_t ks_b = smem_b + FL_KS * 4;
    uint32_t vs_b = smem_b + FL_VS * 4;

    // staging role: chunk c covers row c>>4, 16B segment c&15
    // ---- stage Q once ----
    #pragma unroll
    for (int i = 0; i < 4; i++) {
        int c = tid + i * 256;
        int row = c >> 4, seg = c & 15;
        CP_ASYNC16(qs_b + (uint32_t)(row * 68 + seg * 4) * 4,
                   Qb + (size_t)row * DD + seg * 4);
    }
    CP_COMMIT();

    // ldmatrix address pieces
    int lm_tile = lane >> 3, lm_r = lane & 7;
    int lm_half = (lm_tile & 1) * 8;          // row offset within 16-row block
    int lm_colw = (lm_tile >> 1) * 4;         // word column offset
    int q_row_base = wm * 32 + lm_half + lm_r;
    int k_row_base = wn * 16 + lm_half + lm_r;

    float acc_o[2][2][4];
    #pragma unroll
    for (int i = 0; i < 2; i++)
        #pragma unroll
        for (int j = 0; j < 2; j++)
            #pragma unroll
            for (int r = 0; r < 4; r++) acc_o[i][j][r] = 0.f;
    float mrow[4], lrow[4];
    #pragma unroll
    for (int i = 0; i < 4; i++) { mrow[i] = -INFINITY; lrow[i] = 0.f; }

    for (int kt = 0; kt < SS / 64; kt++) {
        int k0 = kt * 64;
        __syncthreads();   // prior tile's K/V smem reads complete

        // ---- stage K, V natural (coalesced cp.async) ----
        #pragma unroll
        for (int i = 0; i < 4; i++) {
            int c = tid + i * 256;
            int row = c >> 4, seg = c & 15;
            CP_ASYNC16(ks_b + (uint32_t)(row * 68 + seg * 4) * 4,
                       Kb + (size_t)(k0 + row) * DD + seg * 4);
            CP_ASYNC16(vs_b + (uint32_t)(row * 72 + seg * 4) * 4,
                       Vb + (size_t)(k0 + row) * DD + seg * 4);
        }
        CP_COMMIT();
        if (tid < 64) ms[tid] = mb[k0 + tid];
        CP_WAIT(0);
        __syncthreads();

        // ---- S = Q @ K^T via MMA (ldmatrix fragments) ----
        float sacc[2][2][4];
        #pragma unroll
        for (int i = 0; i < 2; i++)
            #pragma unroll
            for (int j = 0; j < 2; j++)
                #pragma unroll
                for (int r = 0; r < 4; r++) sacc[i][j][r] = 0.f;
        #pragma unroll
        for (int ks = 0; ks < 8; ks++) {
            uint32_t qa[2][4], kfr[4], bfr[2][2];
            #pragma unroll
            for (int im2 = 0; im2 < 2; im2++) {
                int row = q_row_base + im2 * 16;
                uint32_t addr = qs_b + (uint32_t)(row * 68 + ks * 8 + lm_colw) * 4u;
                LDSM_X4(qa[im2][0], qa[im2][1], qa[im2][2], qa[im2][3], addr);
            }
            {
                uint32_t addr = ks_b + (uint32_t)(k_row_base * 68 + ks * 8 + lm_colw) * 4u;
                LDSM_X4(kfr[0], kfr[1], kfr[2], kfr[3], addr);
                bfr[0][0] = kfr[0]; bfr[0][1] = kfr[2];   // jn0: b0, b1
                bfr[1][0] = kfr[1]; bfr[1][1] = kfr[3];   // jn1: b0, b1
            }
            #pragma unroll
            for (int im2 = 0; im2 < 2; im2++)
                #pragma unroll
                for (int jn2 = 0; jn2 < 2; jn2++)
                    MMA_TF32(sacc[im2][jn2], qa[im2], bfr[jn2]);
        }
        // write S tile to smem, applying 1/sqrt(dk)
        #pragma unroll
        for (int im2 = 0; im2 < 2; im2++) {
            int row = wm * 32 + im2 * 16 + g;
            #pragma unroll
            for (int jn2 = 0; jn2 < 2; jn2++) {
                int col = wn * 16 + jn2 * 8 + 2 * t;
                Ss[row * 68 + col]           = sacc[im2][jn2][0] * 0.125f;
                Ss[row * 68 + col + 1]       = sacc[im2][jn2][1] * 0.125f;
                Ss[(row + 8) * 68 + col]     = sacc[im2][jn2][2] * 0.125f;
                Ss[(row + 8) * 68 + col + 1] = sacc[im2][jn2][3] * 0.125f;
            }
        }
        __syncthreads();

        // ---- scalar online softmax (rows ty*4+i, cols tx*4+j) ----
        float s4[4][4];
        #pragma unroll
        for (int i = 0; i < 4; i++) {
            float4 r4 = *(const float4*)&Ss[(ty * 4 + i) * 68 + tx * 4];
            s4[i][0] = r4.x; s4[i][1] = r4.y; s4[i][2] = r4.z; s4[i][3] = r4.w;
        }
        #pragma unroll
        for (int i = 0; i < 4; i++)
            #pragma unroll
            for (int j = 0; j < 4; j++)
                if (ms[tx * 4 + j] == 0) s4[i][j] = -INFINITY;

        float scv[4];
        #pragma unroll
        for (int i = 0; i < 4; i++) {
            float mx = fmaxf(fmaxf(s4[i][0], s4[i][1]), fmaxf(s4[i][2], s4[i][3]));
            #pragma unroll
            for (int off = 8; off; off >>= 1)
                mx = fmaxf(mx, __shfl_xor_sync(0xffffffffu, mx, off));
            float mn = fmaxf(mrow[i], mx);
            float scl = (mrow[i] == -INFINITY) ? 0.f : __expf(mrow[i] - mn);
            float sum = 0.f;
            #pragma unroll
            for (int j = 0; j < 4; j++) {
                float p = __expf(s4[i][j] - mn);
                s4[i][j] = p; sum += p;
            }
            #pragma unroll
            for (int off = 8; off; off >>= 1)
                sum += __shfl_xor_sync(0xffffffffu, sum, off);
            lrow[i] = lrow[i] * scl + sum;
            mrow[i] = mn;
            scv[i] = scl;
        }
        // write P fragments + rescale factors
        #pragma unroll
        for (int i = 0; i < 4; i++) {
            int row = ty * 4 + i;
            int p_im = row >> 4, p_g = row & 7, p_half = (row >> 3) & 1;
            #pragma unroll
            for (int j = 0; j < 4; j++) {
                int col = tx * 4 + j;
                int reg = p_half + 2 * ((col >> 2) & 1);
                int ln  = p_g * 4 + (col & 3);
                Pf[(((col >> 3) * 4 + p_im) * 32 + ln) * 4 + reg] =
                    __float_as_uint(s4[i][j]);
            }
            if (tx == 0) sc[row] = scv[i];
        }
        __syncthreads();

        // ---- O = O*sc + P @ V ----
        #pragma unroll
        for (int im2 = 0; im2 < 2; im2++) {
            int rl = wm * 32 + im2 * 16 + g;
            float s0 = sc[rl], s1 = sc[rl + 8];
            #pragma unroll
            for (int jn2 = 0; jn2 < 2; jn2++) {
                acc_o[im2][jn2][0] *= s0; acc_o[im2][jn2][1] *= s0;
                acc_o[im2][jn2][2] *= s1; acc_o[im2][jn2][3] *= s1;
            }
        }
        #pragma unroll
        for (int ks = 0; ks < 8; ks++) {
            uint32_t pa[2][4], vb2[2][2];
            #pragma unroll
            for (int im2 = 0; im2 < 2; im2++)
                *(uint4*)&pa[im2][0] =
                    *(const uint4*)&Pf[((ks * 4 + wm * 2 + im2) * 32 + lane) * 4];
            // V fragments: conflict-free scalar LDS from natural pad-72 layout
            #pragma unroll
            for (int jn2 = 0; jn2 < 2; jn2++) {
                int col = wn * 16 + jn2 * 8 + g;
                vb2[jn2][0] = __float_as_uint(Vs[(ks * 8 + t    ) * 72 + col]);
                vb2[jn2][1] = __float_as_uint(Vs[(ks * 8 + t + 4) * 72 + col]);
            }
            #pragma unroll
            for (int im2 = 0; im2 < 2; im2++)
                #pragma unroll
                for (int jn2 = 0; jn2 < 2; jn2++)
                    MMA_TF32(acc_o[im2][jn2], pa[im2], vb2[jn2]);
        }
    }

    __syncthreads();
    #pragma unroll
    for (int i = 0; i < 4; i++)
        if (tx == 0) li[ty * 4 + i] = 1.0f / lrow[i];
    __syncthreads();

    float* Ob = O + ((size_t)(b * SS + q0)) * DD + h * DK;
    #pragma unroll
    for (int im2 = 0; im2 < 2; im2++) {
        int rl = wm * 32 + im2 * 16 + g;
        float il0 = li[rl], il1 = li[rl + 8];
        #pragma unroll
        for (int jn2 = 0; jn2 < 2; jn2++) {
            int col = wn * 16 + jn2 * 8 + 2 * t;
            *(float2*)(Ob + (size_t)rl * DD + col) =
                make_float2(acc_o[im2][jn2][0] * il0, acc_o[im2][jn2][1] * il0);
            *(float2*)(Ob + (size_t)(rl + 8) * DD + col) =
                make_float2(acc_o[im2][jn2][2] * il1, acc_o[im2][jn2][3] * il1);
        }
    }
}

// ---------------- launch ------------------------------------------------------
extern "C" void kernel_launch(void* const* d_in, const int* in_sizes, int n_in,
                              void* d_out, int out_size)
{
    const float* x    = (const float*)d_in[0];
    const int*   mask = (const int*)  d_in[1];
    const float* wq   = (const float*)d_in[2];
    const float* bq   = (const float*)d_in[3];
    const float* wk   = (const float*)d_in[4];
    const float* bk   = (const float*)d_in[5];
    const float* wv   = (const float*)d_in[6];
    const float* bv   = (const float*)d_in[7];
    const float* wo   = (const float*)d_in[8];
    const float* bo   = (const float*)d_in[9];
    const float* w1   = (const float*)d_in[10];
    const float* b1   = (const float*)d_in[11];
    const float* w2   = (const float*)d_in[12];
    const float* b2   = (const float*)d_in[13];
    const float* ln1w = (const float*)d_in[14];
    const float* ln1b = (const float*)d_in[15];
    const float* ln2w = (const float*)d_in[16];
    const float* ln2b = (const float*)d_in[17];
    float* out = (float*)d_out;

    float *xn, *q, *k, *v, *attn, *x1, *hb;
    uint32_t* wf;
    cudaGetSymbolAddress((void**)&xn,   g_xn);
    cudaGetSymbolAddress((void**)&q,    g_q);
    cudaGetSymbolAddress((void**)&k,    g_k);
    cudaGetSymbolAddress((void**)&v,    g_v);
    cudaGetSymbolAddress((void**)&attn, g_attn);
    cudaGetSymbolAddress((void**)&x1,   g_x1);
    cudaGetSymbolAddress((void**)&hb,   g_h);
    cudaGetSymbolAddress((void**)&wf,   g_wf);

    cudaFuncSetAttribute(flash_kernel,
                         cudaFuncAttributeMaxDynamicSharedMemorySize,
                         FL_TOT * (int)sizeof(uint32_t));
    cudaFuncSetAttribute(tgemm_kernel<1>,
                         cudaFuncAttributeMaxDynamicSharedMemorySize, GSMEM_BYTES);
    cudaFuncSetAttribute(tgemm_kernel<2>,
                         cudaFuncAttributeMaxDynamicSharedMemorySize, GSMEM_BYTES);
    cudaFuncSetAttribute(qkv_kernel,
                         cudaFuncAttributeMaxDynamicSharedMemorySize, GSMEM_BYTES);

    dim3 gD  (DD  / 128, NROW / 128);
    dim3 gQKV(DD  / 128, NROW / 128, 3);
    dim3 gF  (DFF / 128, NROW / 128);
    dim3 gAtt(SS / 64, HH, BB);

    // 0) weight fragment pre-layout
    wlayout_kernel<<<dim3(DD  / 8, DD  / 32), 64>>>(wq, wf + WF_Q, DD);
    wlayout_kernel<<<dim3(DD  / 8, DD  / 32), 64>>>(wk, wf + WF_K, DD);
    wlayout_kernel<<<dim3(DD  / 8, DD  / 32), 64>>>(wv, wf + WF_V, DD);
    wlayout_kernel<<<dim3(DD  / 8, DD  / 32), 64>>>(wo, wf + WF_O, DD);
    wlayout_kernel<<<dim3(DFF / 8, DD  / 32), 64>>>(w1, wf + WF_1, DFF);
    wlayout_kernel<<<dim3(DD  / 8, DFF / 32), 64>>>(w2, wf + WF_2, DD);

    // 1) ln1
    ln_kernel<<<NROW, 256>>>(x, ln1w, ln1b, xn);
    // 2) fused QKV
    qkv_kernel<<<gQKV, 256, GSMEM_BYTES>>>(xn, wf, bq, bk, bv, q, k, v);
    // 3) attention
    flash_kernel<<<gAtt, 256, FL_TOT * sizeof(uint32_t)>>>(q, k, v, mask, attn);
    // 4) output projection + residual
    tgemm_kernel<2><<<gD, 256, GSMEM_BYTES>>>(attn, wf + WF_O, bo, x, x1, DD, DD);
    // 5) ln2
    ln_kernel<<<NROW, 256>>>(x1, ln2w, ln2b, xn);
    // 6) FFN up + relu
    tgemm_kernel<1><<<gF, 256, GSMEM_BYTES>>>(xn, wf + WF_1, b1, nullptr, hb, DD, DFF);
    // 7) FFN down + residual -> out
    tgemm_kernel<2><<<gD, 256, GSMEM_BYTES>>>(hb, wf + WF_2, b2, x1, out, DFF, DD);
}

// round 10
// speedup vs baseline: 3.3398x; 1.3409x over previous
#include <cuda_runtime.h>
#include <math.h>
#include <stdint.h>

// Problem dims (fixed by reference)
#define BB   4
#define SS   2048
#define DD   1024
#define HH   16
#define DK   64
#define DFF  4096
#define NROW (BB*SS)          // 8192
#define LEPS 1e-6f

// ---------------- scratch (static __device__, no allocations) ----------------
__device__ float g_xn  [(size_t)NROW * DD];
__device__ float g_q   [(size_t)NROW * DD];
__device__ float g_k   [(size_t)NROW * DD];
__device__ float g_v   [(size_t)NROW * DD];
__device__ float g_attn[(size_t)NROW * DD];
__device__ float g_x1  [(size_t)NROW * DD];
__device__ float g_h   [(size_t)NROW * DFF];
// pre-laid tf32 weight fragments: wq,wk,wv,wo (1M each), w1 (4M), w2 (4M)
__device__ uint32_t g_wf[(size_t)13 * 1024 * 1024];

#define WF_Q  ((size_t)0)
#define WF_K  ((size_t)1  * 1024 * 1024)
#define WF_V  ((size_t)2  * 1024 * 1024)
#define WF_O  ((size_t)3  * 1024 * 1024)
#define WF_1  ((size_t)4  * 1024 * 1024)
#define WF_2  ((size_t)8  * 1024 * 1024)

// ---------------- helpers -----------------------------------------------------
__device__ __forceinline__ uint32_t f2tf(float f) {
    uint32_t u;
    asm("cvt.rna.tf32.f32 %0, %1;" : "=r"(u) : "f"(f));
    return u;
}

#define MMA_TF32(d, a, b)                                                     \
    asm volatile("mma.sync.aligned.m16n8k8.row.col.f32.tf32.tf32.f32 "        \
                 "{%0,%1,%2,%3},{%4,%5,%6,%7},{%8,%9},{%0,%1,%2,%3};"         \
                 : "+f"(d[0]), "+f"(d[1]), "+f"(d[2]), "+f"(d[3])             \
                 : "r"(a[0]), "r"(a[1]), "r"(a[2]), "r"(a[3]),                \
                   "r"(b[0]), "r"(b[1]))

#define LDSM_X4(r0, r1, r2, r3, addr)                                         \
    asm volatile("ldmatrix.sync.aligned.m8n8.x4.shared.b16 {%0,%1,%2,%3}, [%4];" \
                 : "=r"(r0), "=r"(r1), "=r"(r2), "=r"(r3) : "r"(addr))

#define CP_ASYNC16(dst, src)                                                  \
    asm volatile("cp.async.ca.shared.global [%0], [%1], 16;"                  \
                 :: "r"(dst), "l"(src))
#define CP_COMMIT() asm volatile("cp.async.commit_group;")
#define CP_WAIT(n)  asm volatile("cp.async.wait_group %0;" :: "n"(n))

// ---------------- weight fragment pre-layout (MLP=4) ---------------------------
__global__ void wlayout_kernel(const float* __restrict__ W,
                               uint32_t* __restrict__ Wf, int M)
{
    int mb = blockIdx.x;
    int kb0 = blockIdx.y * 4;
    int tid = threadIdx.x;                 // 64 threads
    int lane = tid & 31, reg = tid >> 5;
    int t = lane & 3, g = lane >> 2;
    #pragma unroll
    for (int i = 0; i < 4; i++) {
        int kb = kb0 + i;
        float v = W[(size_t)(kb * 8 + t + reg * 4) * M + mb * 8 + g];
        Wf[(((size_t)kb * (M >> 3)) + mb) * 64 + lane * 2 + reg] = f2tf(v);
    }
}

// ---------------- LayerNorm (ddof=1, divide by std+eps) ----------------------
__global__ void ln_kernel(const float* __restrict__ x,
                          const float* __restrict__ w,
                          const float* __restrict__ b,
                          float* __restrict__ y)
{
    int row = blockIdx.x;
    const float* xr = x + (size_t)row * DD;
    int c = threadIdx.x * 4;
    float4 v = *(const float4*)(xr + c);
    float s  = v.x + v.y + v.z + v.w;
    float sq = v.x*v.x + v.y*v.y + v.z*v.z + v.w*v.w;
    #pragma unroll
    for (int o = 16; o; o >>= 1) {
        s  += __shfl_xor_sync(0xffffffffu, s,  o);
        sq += __shfl_xor_sync(0xffffffffu, sq, o);
    }
    __shared__ float ssm[8], sqm[8];
    int wid = threadIdx.x >> 5, lid = threadIdx.x & 31;
    if (lid == 0) { ssm[wid] = s; sqm[wid] = sq; }
    __syncthreads();
    if (wid == 0) {
        float a = (lid < 8) ? ssm[lid] : 0.f;
        float q = (lid < 8) ? sqm[lid] : 0.f;
        #pragma unroll
        for (int o = 16; o; o >>= 1) {
            a += __shfl_xor_sync(0xffffffffu, a, o);
            q += __shfl_xor_sync(0xffffffffu, q, o);
        }
        if (lid == 0) { ssm[0] = a; sqm[0] = q; }
    }
    __syncthreads();
    float sum = ssm[0], sumsq = sqm[0];
    float mean = sum * (1.0f / DD);
    float var  = (sumsq - sum * mean) * (1.0f / (DD - 1));
    float inv  = 1.0f / (sqrtf(var) + LEPS);

    float4 wv = *(const float4*)(w + c);
    float4 bv = *(const float4*)(b + c);
    float4 out;
    out.x = wv.x * (v.x - mean) * inv + bv.x;
    out.y = wv.y * (v.y - mean) * inv + bv.y;
    out.z = wv.z * (v.z - mean) * inv + bv.z;
    out.w = wv.w * (v.w - mean) * inv + bv.w;
    *(float4*)(y + (size_t)row * DD + c) = out;
}

// ---------------- TF32 GEMM: 4-stage cp.async pipeline (unchanged R8) ---------
#define STAGES    4
#define AS_WORDS  2560
#define BS_WORDS  2048
#define STG_WORDS (AS_WORDS + BS_WORDS)
#define GSMEM_BYTES (STAGES * STG_WORDS * 4)

template<int MODE>
__device__ __forceinline__
void tgemm_body(const float* __restrict__ A, const uint32_t* __restrict__ Wf,
                const float* __restrict__ bias, const float* __restrict__ resid,
                float* __restrict__ C, int K, int M, int bx, int by)
{
    extern __shared__ __align__(16) uint32_t dsm[];

    int tid  = threadIdx.x;
    int lane = tid & 31, warp = tid >> 5;
    int wm = warp >> 2, wn = warp & 3;
    int g = lane >> 2, t = lane & 3;
    int row0 = by * 128, col0 = bx * 128;
    const int MB = M >> 3;
    const int KT = K >> 4;

    int ar = tid >> 1, aks = tid & 1;
    const float* Aptr = A + (size_t)(row0 + ar) * K + aks * 8;

    int bks = tid >> 7;
    int bidx = (tid & 127) * 8;
    const uint32_t* Wfp = Wf + ((size_t)bks * MB + (col0 >> 3)) * 64 + bidx;
    const size_t wstep = (size_t)2 * MB * 64;

    uint32_t smem_u32 = (uint32_t)__cvta_generic_to_shared(dsm);
    uint32_t a_dst = smem_u32 + (uint32_t)(ar * 20 + aks * 8) * 4;
    uint32_t b_dst = smem_u32 + (uint32_t)(AS_WORDS + bks * 1024 + bidx) * 4;

    int lm_tile = lane >> 3, lm_r = lane & 7;
    int lm_row_base = wm * 64 + (lm_tile & 1) * 8 + lm_r;
    int lm_colw = (lm_tile >> 1) * 4;

    float acc[4][4][4];
    #pragma unroll
    for (int i = 0; i < 4; i++)
        #pragma unroll
        for (int j = 0; j < 4; j++)
            #pragma unroll
            for (int r = 0; r < 4; r++) acc[i][j][r] = 0.f;

    #pragma unroll
    for (int s = 0; s < STAGES - 1; s++) {
        uint32_t soff = (uint32_t)(s * STG_WORDS) * 4;
        const float* asrc = Aptr + s * 16;
        CP_ASYNC16(a_dst + soff,      asrc);
        CP_ASYNC16(a_dst + soff + 16, asrc + 4);
        const uint32_t* bsrc = Wfp + (size_t)s * wstep;
        CP_ASYNC16(b_dst + soff,      bsrc);
        CP_ASYNC16(b_dst + soff + 16, bsrc + 4);
        CP_COMMIT();
    }

    for (int kt = 0; kt < KT; kt++) {
        CP_WAIT(STAGES - 2);
        __syncthreads();

        int pf = kt + STAGES - 1;
        if (pf < KT) {
            uint32_t soff = (uint32_t)((pf & (STAGES - 1)) * STG_WORDS) * 4;
            const float* asrc = Aptr + pf * 16;
            CP_ASYNC16(a_dst + soff,      asrc);
            CP_ASYNC16(a_dst + soff + 16, asrc + 4);
            const uint32_t* bsrc = Wfp + (size_t)pf * wstep;
            CP_ASYNC16(b_dst + soff,      bsrc);
            CP_ASYNC16(b_dst + soff + 16, bsrc + 4);
        }
        CP_COMMIT();

        int cs = kt & (STAGES - 1);
        uint32_t as_base = smem_u32 + (uint32_t)(cs * STG_WORDS) * 4;
        const uint32_t* BfS = dsm + cs * STG_WORDS + AS_WORDS;

        #pragma unroll
        for (int ks = 0; ks < 2; ks++) {
            uint32_t afr[4][4], bfr[4][2];
            #pragma unroll
            for (int im = 0; im < 4; im++) {
                int row = lm_row_base + im * 16;
                uint32_t addr = as_base + (uint32_t)(row * 20 + ks * 8 + lm_colw) * 4u;
                LDSM_X4(afr[im][0], afr[im][1], afr[im][2], afr[im][3], addr);
            }
            #pragma unroll
            for (int jn = 0; jn < 4; jn++)
                *(uint2*)&bfr[jn][0] =
                    *(const uint2*)&BfS[ks * 1024 + (wn * 4 + jn) * 64 + lane * 2];
            #pragma unroll
            for (int im = 0; im < 4; im++)
                #pragma unroll
                for (int jn = 0; jn < 4; jn++)
                    MMA_TF32(acc[im][jn], afr[im], bfr[jn]);
        }
    }

    #pragma unroll
    for (int im = 0; im < 4; im++) {
        int rA = row0 + wm * 64 + im * 16 + g;
        int rB = rA + 8;
        #pragma unroll
        for (int jn = 0; jn < 4; jn++) {
            int col = col0 + wn * 32 + jn * 8 + 2 * t;
            float bx0 = bias[col], bx1 = bias[col + 1];
            float v0 = acc[im][jn][0] + bx0;
            float v1 = acc[im][jn][1] + bx1;
            float v2 = acc[im][jn][2] + bx0;
            float v3 = acc[im][jn][3] + bx1;
            if (MODE == 1) {
                v0 = fmaxf(v0, 0.f); v1 = fmaxf(v1, 0.f);
                v2 = fmaxf(v2, 0.f); v3 = fmaxf(v3, 0.f);
            }
            size_t oA = (size_t)rA * M + col;
            size_t oB = (size_t)rB * M + col;
            if (MODE == 2) {
                float2 r0 = *(const float2*)(resid + oA);
                float2 r1 = *(const float2*)(resid + oB);
                v0 += r0.x; v1 += r0.y; v2 += r1.x; v3 += r1.y;
            }
            *(float2*)(C + oA) = make_float2(v0, v1);
            *(float2*)(C + oB) = make_float2(v2, v3);
        }
    }
}

template<int MODE>
__global__ __launch_bounds__(256, 2)
void tgemm_kernel(const float* __restrict__ A, const uint32_t* __restrict__ Wf,
                  const float* __restrict__ bias, const float* __restrict__ resid,
                  float* __restrict__ C, int K, int M)
{
    tgemm_body<MODE>(A, Wf, bias, resid, C, K, M, blockIdx.x, blockIdx.y);
}

__global__ __launch_bounds__(256, 2)
void qkv_kernel(const float* __restrict__ A, const uint32_t* __restrict__ wf,
                const float* __restrict__ bq, const float* __restrict__ bk,
                const float* __restrict__ bv,
                float* __restrict__ q, float* __restrict__ k, float* __restrict__ v)
{
    const uint32_t* W; const float* bias; float* C;
    if (blockIdx.z == 0)      { W = wf + WF_Q; bias = bq; C = q; }
    else if (blockIdx.z == 1) { W = wf + WF_K; bias = bk; C = k; }
    else                      { W = wf + WF_V; bias = bv; C = v; }
    tgemm_body<0>(A, W, bias, nullptr, C, DD, DD, blockIdx.x, blockIdx.y);
}

// ---------------- Flash attention v3: register-resident softmax ----------------
// Br=Bc=64, dk=64. 128 threads = 4 warps, each warp owns 16 FULL rows
// (warp tile 16 x 64 for both S and O). Softmax entirely in fragment
// registers; P built for PV via shuffles. Smem: only Q/K/V natural tiles.
#define FL_QS 0            // Q: 64 x 68
#define FL_KS 4352         // K: 64 x 68
#define FL_VS 8704         // V: 64 x 72
#define FL_MS 13312        // mask[64]
#define FL_TOT 13376       // *4 = 53504 bytes

__global__ __launch_bounds__(128)
void flash_kernel(const float* __restrict__ Q, const float* __restrict__ Kk,
                  const float* __restrict__ V, const int* __restrict__ mask,
                  float* __restrict__ O)
{
    extern __shared__ __align__(16) uint32_t smu[];
    float* Vs = (float*)(smu + FL_VS);
    int*   ms = (int*)  (smu + FL_MS);

    int tid  = threadIdx.x;
    int lane = tid & 31, wm = tid >> 5;     // 4 warps, each 16 rows
    int g = lane >> 2, t = lane & 3;

    int q0 = blockIdx.x * 64;
    int h  = blockIdx.y;
    int b  = blockIdx.z;

    const float* Qb = Q  + ((size_t)(b * SS + q0)) * DD + h * DK;
    const float* Kb = Kk + ((size_t)b * SS) * DD + h * DK;
    const float* Vb = V  + ((size_t)b * SS) * DD + h * DK;
    const int*   mb = mask + b * SS;

    uint32_t smem_b = (uint32_t)__cvta_generic_to_shared(smu);
    uint32_t qs_b = smem_b + FL_QS * 4;
    uint32_t ks_b = smem_b + FL_KS * 4;
    uint32_t vs_b = smem_b + FL_VS * 4;

    // ---- stage Q once: 64 rows x 64 floats, 8 chunks of 16B per thread ----
    #pragma unroll
    for (int i = 0; i < 8; i++) {
        int c = tid + i * 128;
        int row = c >> 4, seg = c & 15;
        CP_ASYNC16(qs_b + (uint32_t)(row * 68 + seg * 4) * 4,
                   Qb + (size_t)row * DD + seg * 4);
    }
    CP_COMMIT();

    // ldmatrix address pieces
    int lm_tile = lane >> 3, lm_r = lane & 7;
    int lm_half = (lm_tile & 1) * 8;
    int lm_colw = (lm_tile >> 1) * 4;
    int q_row = wm * 16 + lm_half + lm_r;

    // shuffle source lanes for P fragment construction
    int srcA = g * 4 + (t >> 1);        // col t
    int srcB = srcA + 2;                // col t+4
    int podd = t & 1;

    float acc_o[8][4];
    #pragma unroll
    for (int j = 0; j < 8; j++)
        #pragma unroll
        for (int r = 0; r < 4; r++) acc_o[j][r] = 0.f;
    float m0 = -INFINITY, m1 = -INFINITY, l0 = 0.f, l1 = 0.f;

    for (int kt = 0; kt < SS / 64; kt++) {
        int k0 = kt * 64;
        __syncthreads();   // previous tile's K/V reads complete

        #pragma unroll
        for (int i = 0; i < 8; i++) {
            int c = tid + i * 128;
            int row = c >> 4, seg = c & 15;
            CP_ASYNC16(ks_b + (uint32_t)(row * 68 + seg * 4) * 4,
                       Kb + (size_t)(k0 + row) * DD + seg * 4);
            CP_ASYNC16(vs_b + (uint32_t)(row * 72 + seg * 4) * 4,
                       Vb + (size_t)(k0 + row) * DD + seg * 4);
        }
        CP_COMMIT();
        if (tid < 64) ms[tid] = mb[k0 + tid];
        CP_WAIT(0);
        __syncthreads();

        // ---- S = Q @ K^T : warp tile 16 x 64 ----
        float sacc[8][4];
        #pragma unroll
        for (int j = 0; j < 8; j++)
            #pragma unroll
            for (int r = 0; r < 4; r++) sacc[j][r] = 0.f;
        #pragma unroll
        for (int ks = 0; ks < 8; ks++) {
            uint32_t qa[4];
            {
                uint32_t addr = qs_b + (uint32_t)(q_row * 68 + ks * 8 + lm_colw) * 4u;
                LDSM_X4(qa[0], qa[1], qa[2], qa[3], addr);
            }
            #pragma unroll
            for (int kb = 0; kb < 4; kb++) {
                uint32_t kfr[4];
                int krow = kb * 16 + lm_half + lm_r;
                uint32_t addr = ks_b + (uint32_t)(krow * 68 + ks * 8 + lm_colw) * 4u;
                LDSM_X4(kfr[0], kfr[1], kfr[2], kfr[3], addr);
                uint32_t b0[2] = {kfr[0], kfr[2]};
                uint32_t b1[2] = {kfr[1], kfr[3]};
                MMA_TF32(sacc[kb * 2],     qa, b0);
                MMA_TF32(sacc[kb * 2 + 1], qa, b1);
            }
        }

        // ---- scale + mask (rows: r0 = wm*16+g, r1 = r0+8; cols jn*8+2t,+1) --
        #pragma unroll
        for (int jn = 0; jn < 8; jn++) {
            int col = jn * 8 + 2 * t;
            bool z0 = (ms[col] == 0), z1 = (ms[col + 1] == 0);
            sacc[jn][0] = z0 ? -INFINITY : sacc[jn][0] * 0.125f;
            sacc[jn][1] = z1 ? -INFINITY : sacc[jn][1] * 0.125f;
            sacc[jn][2] = z0 ? -INFINITY : sacc[jn][2] * 0.125f;
            sacc[jn][3] = z1 ? -INFINITY : sacc[jn][3] * 0.125f;
        }

        // ---- in-register online softmax ----
        float mx0 = -INFINITY, mx1 = -INFINITY;
        #pragma unroll
        for (int jn = 0; jn < 8; jn++) {
            mx0 = fmaxf(mx0, fmaxf(sacc[jn][0], sacc[jn][1]));
            mx1 = fmaxf(mx1, fmaxf(sacc[jn][2], sacc[jn][3]));
        }
        mx0 = fmaxf(mx0, __shfl_xor_sync(0xffffffffu, mx0, 1));
        mx0 = fmaxf(mx0, __shfl_xor_sync(0xffffffffu, mx0, 2));
        mx1 = fmaxf(mx1, __shfl_xor_sync(0xffffffffu, mx1, 1));
        mx1 = fmaxf(mx1, __shfl_xor_sync(0xffffffffu, mx1, 2));

        float mn0 = fmaxf(m0, mx0), mn1 = fmaxf(m1, mx1);
        float sc0 = (m0 == -INFINITY) ? 0.f : __expf(m0 - mn0);
        float sc1 = (m1 == -INFINITY) ? 0.f : __expf(m1 - mn1);
        float sum0 = 0.f, sum1 = 0.f;
        #pragma unroll
        for (int jn = 0; jn < 8; jn++) {
            float p0 = __expf(sacc[jn][0] - mn0);
            float p1 = __expf(sacc[jn][1] - mn0);
            float p2 = __expf(sacc[jn][2] - mn1);
            float p3 = __expf(sacc[jn][3] - mn1);
            sacc[jn][0] = p0; sacc[jn][1] = p1;
            sacc[jn][2] = p2; sacc[jn][3] = p3;
            sum0 += p0 + p1; sum1 += p2 + p3;
        }
        sum0 += __shfl_xor_sync(0xffffffffu, sum0, 1);
        sum0 += __shfl_xor_sync(0xffffffffu, sum0, 2);
        sum1 += __shfl_xor_sync(0xffffffffu, sum1, 1);
        sum1 += __shfl_xor_sync(0xffffffffu, sum1, 2);
        l0 = l0 * sc0 + sum0;  m0 = mn0;
        l1 = l1 * sc1 + sum1;  m1 = mn1;

        // rescale O accumulators
        #pragma unroll
        for (int jn = 0; jn < 8; jn++) {
            acc_o[jn][0] *= sc0; acc_o[jn][1] *= sc0;
            acc_o[jn][2] *= sc1; acc_o[jn][3] *= sc1;
        }

        // ---- O += P @ V : P fragments via shuffles, V via scalar LDS ----
        #pragma unroll
        for (int ks = 0; ks < 8; ks++) {
            // A-fragment: a0=P[g][8ks+t] a1=P[g+8][8ks+t] a2=P[g][8ks+t+4] a3=...
            float c0 = sacc[ks][0], c1 = sacc[ks][1];
            float c2 = sacc[ks][2], c3 = sacc[ks][3];
            float x0 = __shfl_sync(0xffffffffu, c0, srcA);
            float x1 = __shfl_sync(0xffffffffu, c1, srcA);
            float y0 = __shfl_sync(0xffffffffu, c0, srcB);
            float y1 = __shfl_sync(0xffffffffu, c1, srcB);
            float x2 = __shfl_sync(0xffffffffu, c2, srcA);
            float x3 = __shfl_sync(0xffffffffu, c3, srcA);
            float y2 = __shfl_sync(0xffffffffu, c2, srcB);
            float y3 = __shfl_sync(0xffffffffu, c3, srcB);
            uint32_t pa[4];
            pa[0] = __float_as_uint(podd ? x1 : x0);
            pa[1] = __float_as_uint(podd ? x3 : x2);
            pa[2] = __float_as_uint(podd ? y1 : y0);
            pa[3] = __float_as_uint(podd ? y3 : y2);

            int vr0 = (ks * 8 + t) * 72, vr1 = (ks * 8 + t + 4) * 72;
            #pragma unroll
            for (int jn = 0; jn < 8; jn++) {
                int col = jn * 8 + g;
                uint32_t vb[2];
                vb[0] = __float_as_uint(Vs[vr0 + col]);
                vb[1] = __float_as_uint(Vs[vr1 + col]);
                MMA_TF32(acc_o[jn], pa, vb);
            }
        }
    }

    // ---- finalize: rows wm*16+g (il0), wm*16+g+8 (il1) ----
    float il0 = 1.0f / l0, il1 = 1.0f / l1;
    float* Ob = O + ((size_t)(b * SS + q0)) * DD + h * DK;
    int r0 = wm * 16 + g, r1 = r0 + 8;
    #pragma unroll
    for (int jn = 0; jn < 8; jn++) {
        int col = jn * 8 + 2 * t;
        *(float2*)(Ob + (size_t)r0 * DD + col) =
            make_float2(acc_o[jn][0] * il0, acc_o[jn][1] * il0);
        *(float2*)(Ob + (size_t)r1 * DD + col) =
            make_float2(acc_o[jn][2] * il1, acc_o[jn][3] * il1);
    }
}

// ---------------- launch ------------------------------------------------------
extern "C" void kernel_launch(void* const* d_in, const int* in_sizes, int n_in,
                              void* d_out, int out_size)
{
    const float* x    = (const float*)d_in[0];
    const int*   mask = (const int*)  d_in[1];
    const float* wq   = (const float*)d_in[2];
    const float* bq   = (const float*)d_in[3];
    const float* wk   = (const float*)d_in[4];
    const float* bk   = (const float*)d_in[5];
    const float* wv   = (const float*)d_in[6];
    const float* bv   = (const float*)d_in[7];
    const float* wo   = (const float*)d_in[8];
    const float* bo   = (const float*)d_in[9];
    const float* w1   = (const float*)d_in[10];
    const float* b1   = (const float*)d_in[11];
    const float* w2   = (const float*)d_in[12];
    const float* b2   = (const float*)d_in[13];
    const float* ln1w = (const float*)d_in[14];
    const float* ln1b = (const float*)d_in[15];
    const float* ln2w = (const float*)d_in[16];
    const float* ln2b = (const float*)d_in[17];
    float* out = (float*)d_out;

    float *xn, *q, *k, *v, *attn, *x1, *hb;
    uint32_t* wf;
    cudaGetSymbolAddress((void**)&xn,   g_xn);
    cudaGetSymbolAddress((void**)&q,    g_q);
    cudaGetSymbolAddress((void**)&k,    g_k);
    cudaGetSymbolAddress((void**)&v,    g_v);
    cudaGetSymbolAddress((void**)&attn, g_attn);
    cudaGetSymbolAddress((void**)&x1,   g_x1);
    cudaGetSymbolAddress((void**)&hb,   g_h);
    cudaGetSymbolAddress((void**)&wf,   g_wf);

    cudaFuncSetAttribute(flash_kernel,
                         cudaFuncAttributeMaxDynamicSharedMemorySize,
                         FL_TOT * (int)sizeof(uint32_t));
    cudaFuncSetAttribute(tgemm_kernel<1>,
                         cudaFuncAttributeMaxDynamicSharedMemorySize, GSMEM_BYTES);
    cudaFuncSetAttribute(tgemm_kernel<2>,
                         cudaFuncAttributeMaxDynamicSharedMemorySize, GSMEM_BYTES);
    cudaFuncSetAttribute(qkv_kernel,
                         cudaFuncAttributeMaxDynamicSharedMemorySize, GSMEM_BYTES);

    dim3 gD  (DD  / 128, NROW / 128);
    dim3 gQKV(DD  / 128, NROW / 128, 3);
    dim3 gF  (DFF / 128, NROW / 128);
    dim3 gAtt(SS / 64, HH, BB);

    // 0) weight fragment pre-layout
    wlayout_kernel<<<dim3(DD  / 8, DD  / 32), 64>>>(wq, wf + WF_Q, DD);
    wlayout_kernel<<<dim3(DD  / 8, DD  / 32), 64>>>(wk, wf + WF_K, DD);
    wlayout_kernel<<<dim3(DD  / 8, DD  / 32), 64>>>(wv, wf + WF_V, DD);
    wlayout_kernel<<<dim3(DD  / 8, DD  / 32), 64>>>(wo, wf + WF_O, DD);
    wlayout_kernel<<<dim3(DFF / 8, DD  / 32), 64>>>(w1, wf + WF_1, DFF);
    wlayout_kernel<<<dim3(DD  / 8, DFF / 32), 64>>>(w2, wf + WF_2, DD);

    // 1) ln1
    ln_kernel<<<NROW, 256>>>(x, ln1w, ln1b, xn);
    // 2) fused QKV
    qkv_kernel<<<gQKV, 256, GSMEM_BYTES>>>(xn, wf, bq, bk, bv, q, k, v);
    // 3) attention
    flash_kernel<<<gAtt, 128, FL_TOT * sizeof(uint32_t)>>>(q, k, v, mask, attn);
    // 4) output projection + residual
    tgemm_kernel<2><<<gD, 256, GSMEM_BYTES>>>(attn, wf + WF_O, bo, x, x1, DD, DD);
    // 5) ln2
    ln_kernel<<<NROW, 256>>>(x1, ln2w, ln2b, xn);
    // 6) FFN up + relu
    tgemm_kernel<1><<<gF, 256, GSMEM_BYTES>>>(xn, wf + WF_1, b1, nullptr, hb, DD, DFF);
    // 7) FFN down + residual -> out
    tgemm_kernel<2><<<gD, 256, GSMEM_BYTES>>>(hb, wf + WF_2, b2, x1, out, DFF, DD);
}